// round 7
// baseline (speedup 1.0000x reference)
#include <cuda_runtime.h>

#define NB 4
#define NH 16
#define SEQ 2048
#define DIM 1024
#define HD 64
#define SCALE 0.03125f   // 1/sqrt(1024)

typedef unsigned int u32;

// Scratch (allocation-free rule: __device__ globals)
__device__ float g_linv[NB * NH * SEQ];
__device__ float g_att[(size_t)NB * SEQ * DIM];

// ---------------------------------------------------------------------------
// Low-level helpers (portable sm_80+ PTX)
// ---------------------------------------------------------------------------
__device__ __forceinline__ u32 smem_u32(const void* p) {
    u32 a;
    asm("{ .reg .u64 t; cvta.to.shared.u64 t, %1; cvt.u32.u64 %0, t; }"
        : "=r"(a) : "l"(p));
    return a;
}
__device__ __forceinline__ u32 f2tf(float x) {
    u32 r; asm("cvt.rna.tf32.f32 %0, %1;" : "=r"(r) : "f"(x)); return r;
}
__device__ __forceinline__ u32 prmt_hi(u32 a, u32 b) {   // {lo16=a.hi16, hi16=b.hi16}
    u32 r; asm("prmt.b32 %0, %1, %2, 0x7632;" : "=r"(r) : "r"(a), "r"(b)); return r;
}
__device__ __forceinline__ u32 bf16x2_rn(float hi, float lo) {
    u32 r; asm("cvt.rn.bf16x2.f32 %0, %1, %2;" : "=r"(r) : "f"(hi), "f"(lo)); return r;
}
__device__ __forceinline__ float truncb(float x) {       // exact bf16 truncation
    return __uint_as_float(__float_as_uint(x) & 0xFFFF0000u);
}
__device__ __forceinline__ void cpa16(u32 saddr, const void* g) {
    asm volatile("cp.async.ca.shared.global [%0], [%1], 16;" :: "r"(saddr), "l"(g));
}
#define CP_COMMIT() asm volatile("cp.async.commit_group;" ::: "memory")
#define CP_WAIT0()  asm volatile("cp.async.wait_group 0;" ::: "memory")

// m16n8k8 tf32 mma
__device__ __forceinline__ void mma8(float c[4], uint4 a, uint2 b) {
    asm volatile(
        "mma.sync.aligned.m16n8k8.row.col.f32.tf32.tf32.f32 "
        "{%0,%1,%2,%3}, {%4,%5,%6,%7}, {%8,%9}, {%0,%1,%2,%3};"
        : "+f"(c[0]), "+f"(c[1]), "+f"(c[2]), "+f"(c[3])
        : "r"(a.x), "r"(a.y), "r"(a.z), "r"(a.w), "r"(b.x), "r"(b.y));
}
// m16n8k16 bf16 mma
__device__ __forceinline__ void mma16(float c[4], uint4 a, uint2 b) {
    asm volatile(
        "mma.sync.aligned.m16n8k16.row.col.f32.bf16.bf16.f32 "
        "{%0,%1,%2,%3}, {%4,%5,%6,%7}, {%8,%9}, {%0,%1,%2,%3};"
        : "+f"(c[0]), "+f"(c[1]), "+f"(c[2]), "+f"(c[3])
        : "r"(a.x), "r"(a.y), "r"(a.z), "r"(a.w), "r"(b.x), "r"(b.y));
}

// ---------------------------------------------------------------------------
// tf32 fragment packs
// ---------------------------------------------------------------------------
template<int MT>
__device__ __forceinline__ uint4 ldAf(const u32* A, int ks, int mt, int lane) {
    return *(const uint4*)(A + ((size_t)((ks * MT + mt) * 32 + lane)) * 4);
}
template<int NT>
__device__ __forceinline__ uint2 ldBf(const u32* B, int ks, int nt, int lane) {
    return *(const uint2*)(B + ((size_t)((ks * NT + nt) * 32 + lane)) * 2);
}
template<int MT>
__device__ __forceinline__ void stA4(u32* A, int r, int c4, float4 v) {
    int base = (((c4 >> 3) * MT + (r >> 4)) * 32 + ((r & 7) << 2)) * 4
             + (((r >> 3) & 1) | (((c4 >> 2) & 1) << 1));
    A[base + 0]  = f2tf(v.x);
    A[base + 4]  = f2tf(v.y);
    A[base + 8]  = f2tf(v.z);
    A[base + 12] = f2tf(v.w);
}
template<int NT>
__device__ __forceinline__ void stB4_nk(u32* B, int n, int c4, float4 v) {
    int base = (((c4 >> 3) * NT + (n >> 3)) * 32 + ((n & 7) << 2)) * 2
             + ((c4 >> 2) & 1);
    B[base + 0] = f2tf(v.x);
    B[base + 2] = f2tf(v.y);
    B[base + 4] = f2tf(v.z);
    B[base + 6] = f2tf(v.w);
}

// ---------------------------------------------------------------------------
// bf16 fragment packs (m16n8k16).  B-pack padded: stride 33 lane-pairs.
// ---------------------------------------------------------------------------
__device__ __forceinline__ uint4 ldA16(const u32* A, int ks, int mt, int lane) {
    return *(const uint4*)(A + ((size_t)((ks * 8 + mt) * 32 + lane)) * 4);
}
template<int NT>
__device__ __forceinline__ uint2 ldB16(const u32* B, int ks, int nt, int lane) {
    return *(const uint2*)(B + ((size_t)((ks * NT + nt) * 33 + lane)) * 2);
}
__device__ __forceinline__ void stA16_rn(u32* A, int r, int c4, float4 v) {
    int ks = c4 >> 4, kkb = c4 & 15;
    const float* f = &v.x;
#pragma unroll
    for (int p = 0; p < 2; p++) {
        int kk = kkb + 2 * p;
        int c = (kk & 7) >> 1, slot = ((r >> 3) & 1) | ((kk >> 3) << 1);
        int idx = ((ks * 8 + (r >> 4)) * 32 + ((r & 7) << 2) + c) * 4 + slot;
        A[idx] = bf16x2_rn(f[2 * p + 1], f[2 * p]);
    }
}
template<int NT>
__device__ __forceinline__ void stB16_rn(u32* B, int n, int c4, float4 v) {
    int ks = c4 >> 4, kkb = c4 & 15;
    const float* f = &v.x;
#pragma unroll
    for (int p = 0; p < 2; p++) {
        int kk = kkb + 2 * p;
        int c = (kk & 7) >> 1, breg = kk >> 3;
        int idx = ((ks * NT + (n >> 3)) * 33 + ((n & 7) << 2) + c) * 2 + breg;
        B[idx] = bf16x2_rn(f[2 * p + 1], f[2 * p]);
    }
}

// ---------------------------------------------------------------------------
// Kernel 1: l[k] = sum_q exp(s[q,k]); store 1/l. (unchanged — proven 155us)
// ---------------------------------------------------------------------------
__global__ void __launch_bounds__(256) k1_colsum(const float* __restrict__ Qg,
                                                 const float* __restrict__ Kg) {
    extern __shared__ u32 smu[];
    u32* Ka = smu;                       // 4096 u32
    u32* Qb = smu + 4096;                // 4224 u32
    float* colsum = (float*)(smu + 8320);
    int tid = threadIdx.x, lane = tid & 31, w = tid >> 5;
    int wm = w >> 2, wn = w & 3;
    int b = blockIdx.z, h = blockIdx.y, k0 = blockIdx.x << 7;

    const float* Kb = Kg + ((size_t)b * SEQ + k0) * DIM + h * HD;
    const float* Qbase = Qg + (size_t)b * SEQ * DIM + h * HD;

    int rb = tid >> 4, c4 = (tid & 15) << 2;
#pragma unroll
    for (int it = 0; it < 8; it++) {
        int r = rb + (it << 4);
        stA16_rn(Ka, r, c4, *(const float4*)(Kb + (size_t)r * DIM + c4));
    }
    if (tid < 128) colsum[tid] = 0.f;

    float sume[4][2];
#pragma unroll
    for (int i = 0; i < 4; i++) { sume[i][0] = 0.f; sume[i][1] = 0.f; }

    for (int q0 = 0; q0 < SEQ; q0 += 128) {
        __syncthreads();
#pragma unroll
        for (int it = 0; it < 8; it++) {
            int n = rb + (it << 4);
            stB16_rn<16>(Qb, n, c4,
                         *(const float4*)(Qbase + (size_t)(q0 + n) * DIM + c4));
        }
        __syncthreads();

        float acc[4][4][4];
#pragma unroll
        for (int i = 0; i < 4; i++)
#pragma unroll
            for (int j = 0; j < 4; j++)
#pragma unroll
                for (int t = 0; t < 4; t++) acc[i][j][t] = 0.f;

#pragma unroll
        for (int ks = 0; ks < 4; ks++) {
            uint4 af[4]; uint2 bf[4];
#pragma unroll
            for (int i = 0; i < 4; i++) af[i] = ldA16(Ka, ks, wm * 4 + i, lane);
#pragma unroll
            for (int j = 0; j < 4; j++) bf[j] = ldB16<16>(Qb, ks, wn * 4 + j, lane);
#pragma unroll
            for (int i = 0; i < 4; i++)
#pragma unroll
                for (int j = 0; j < 4; j++) mma16(acc[i][j], af[i], bf[j]);
        }
#pragma unroll
        for (int i = 0; i < 4; i++)
#pragma unroll
            for (int j = 0; j < 4; j++) {
                sume[i][0] += __expf(acc[i][j][0] * SCALE) + __expf(acc[i][j][1] * SCALE);
                sume[i][1] += __expf(acc[i][j][2] * SCALE) + __expf(acc[i][j][3] * SCALE);
            }
    }

#pragma unroll
    for (int i = 0; i < 4; i++)
#pragma unroll
        for (int hh = 0; hh < 2; hh++) {
            float v = sume[i][hh];
            v += __shfl_xor_sync(0xffffffffu, v, 1);
            v += __shfl_xor_sync(0xffffffffu, v, 2);
            if ((lane & 3) == 0)
                atomicAdd(&colsum[wm * 64 + i * 16 + (lane >> 2) + hh * 8], v);
        }
    __syncthreads();
    if (tid < 128)
        g_linv[((size_t)b * NH + h) * SEQ + k0 + tid] = 1.0f / colsum[tid];
}

// ---------------------------------------------------------------------------
// k2 helpers: convert raw staged tiles into fragment packs
// ---------------------------------------------------------------------------
__device__ __forceinline__ void k2_convert(const float* __restrict__ SK,
                                           const float* __restrict__ SV,
                                           const float* __restrict__ linv_s,
                                           int k0, u32* Kp, u32* Vh, u32* Vl,
                                           int rb, int c4, int lane) {
#pragma unroll
    for (int it = 0; it < 8; it++) {
        int kt = rb + (it << 4);
        // K row -> tf32 B-pack
        stB4_nk<16>(Kp, kt, c4, *(const float4*)&SK[(kt << 6) + c4]);
        // V row * linv -> bf16 hi/lo B-packs (pair exchange via shfl)
        float rl = linv_s[k0 + kt];
        float4 v = *(const float4*)&SV[(kt << 6) + c4];
        v.x *= rl; v.y *= rl; v.z *= rl; v.w *= rl;
        float4 oth;
        oth.x = __shfl_xor_sync(0xffffffffu, v.x, 16);
        oth.y = __shfl_xor_sync(0xffffffffu, v.y, 16);
        oth.z = __shfl_xor_sync(0xffffffffu, v.z, 16);
        oth.w = __shfl_xor_sync(0xffffffffu, v.w, 16);
        float4 ve, vo;
        if (lane & 16) { ve = oth; vo = v; } else { ve = v; vo = oth; }
        int ke = kt & ~1;
        int ksv = ke >> 4, kk = ke & 15;
        int c = (kk & 7) >> 1, breg = kk >> 3;
        const float* pe = &ve.x; const float* po = &vo.x;
#pragma unroll
        for (int j = 0; j < 4; j++) {
            int d = c4 + j;
            int idx = ((ksv * 8 + (d >> 3)) * 33 + ((d & 7) << 2) + c) * 2 + breg;
            float a = pe[j], bb = po[j];
            if (!(lane & 16))
                Vh[idx] = prmt_hi(__float_as_uint(a), __float_as_uint(bb));
            else
                Vl[idx] = bf16x2_rn(bb - truncb(bb), a - truncb(a));
        }
    }
}

// ---------------------------------------------------------------------------
// Kernel 2: out[q,:] = sum_k exp(s[q,k]) * (linv[k]*v[k,:]).
// cp.async pipeline: tile t+1 streams into raw smem staging during the gemm
// phase of tile t; conversion smem->packs runs after. Register footprint of
// the compute phase identical to round 5.
// gemm1 tf32 (warp = 16q x 128k), P -> bf16 hi/lo in regs,
// gemm2 3-pass bf16 (Ph*Vh + Ph*Vl + Pl*Vh).
// ---------------------------------------------------------------------------
__global__ void __launch_bounds__(256) k2_attnv(const float* __restrict__ Qg,
                                                const float* __restrict__ Kg,
                                                const float* __restrict__ Vg) {
    extern __shared__ u32 smu[];
    u32* Qa = smu;                         // tf32 A-pack 128q x 64d : 8192
    u32* Kp = smu + 8192;                  // tf32 B-pack : 8192
    u32* Vh = smu + 16384;                 // bf16 B-pack : 4224
    u32* Vl = smu + 20608;                 // bf16 B-pack : 4224
    float* SK = (float*)(smu + 24832);     // raw K staging 128x64 : 8192
    float* SV = (float*)(smu + 33024);     // raw V staging 128x64 : 8192
    float* linv_s = (float*)(smu + 41216); // 2048
    // total 43264 u32 = 173056 B

    int tid = threadIdx.x, lane = tid & 31, w = tid >> 5;
    int b = blockIdx.z, h = blockIdx.y, q0 = blockIdx.x << 7;

    const float* Qb = Qg + ((size_t)b * SEQ + q0) * DIM + h * HD;
    const float* Kbase = Kg + (size_t)b * SEQ * DIM + h * HD;
    const float* Vbase = Vg + (size_t)b * SEQ * DIM + h * HD;
    const float* linv = g_linv + ((size_t)b * NH + h) * SEQ;

    u32 skb = smem_u32(SK), svb = smem_u32(SV);
    int rb = tid >> 4, c4 = (tid & 15) << 2;

    // issue cp.async for tile 0
#pragma unroll
    for (int it = 0; it < 8; it++) {
        int r = rb + (it << 4);
        u32 so = (u32)(((r << 6) + c4) << 2);
        cpa16(skb + so, Kbase + (size_t)r * DIM + c4);
        cpa16(svb + so, Vbase + (size_t)r * DIM + c4);
    }
    CP_COMMIT();

    // meanwhile: Q -> tf32 A-pack, linv row -> smem
#pragma unroll
    for (int it = 0; it < 8; it++) {
        int r = rb + (it << 4);
        stA4<8>(Qa, r, c4, *(const float4*)(Qb + (size_t)r * DIM + c4));
    }
    *(float4*)&linv_s[tid * 4] = *(const float4*)&linv[tid * 4];
    *(float4*)&linv_s[1024 + tid * 4] = *(const float4*)&linv[1024 + tid * 4];

    CP_WAIT0();
    __syncthreads();
    k2_convert(SK, SV, linv_s, 0, Kp, Vh, Vl, rb, c4, lane);
    __syncthreads();

    float o[8][4];
#pragma unroll
    for (int nt = 0; nt < 8; nt++)
#pragma unroll
        for (int t = 0; t < 4; t++) o[nt][t] = 0.f;

    for (int t = 0; t < 16; t++) {
        bool hn = (t < 15);
        int k0n = (t + 1) << 7;

        // stream tile t+1 into staging (zero register residency)
        if (hn) {
#pragma unroll
            for (int it = 0; it < 8; it++) {
                int r = rb + (it << 4);
                u32 so = (u32)(((r << 6) + c4) << 2);
                cpa16(skb + so, Kbase + (size_t)(k0n + r) * DIM + c4);
                cpa16(svb + so, Vbase + (size_t)(k0n + r) * DIM + c4);
            }
            CP_COMMIT();
        }

        // gemm1 (tf32): warp w -> q rows [16w,16w+16), all 128 k-cols
        float acc[16][4];
#pragma unroll
        for (int nt = 0; nt < 16; nt++)
#pragma unroll
            for (int tt = 0; tt < 4; tt++) acc[nt][tt] = 0.f;
#pragma unroll
        for (int ks = 0; ks < 8; ks++) {
            uint4 a = ldAf<8>(Qa, ks, w, lane);
#pragma unroll
            for (int nt = 0; nt < 16; nt++) {
                uint2 bf = ldBf<16>(Kp, ks, nt, lane);
                mma8(acc[nt], a, bf);
            }
        }

        // exp -> bf16 hi/lo A-frags in registers; gemm2 immediately
#pragma unroll
        for (int ks2 = 0; ks2 < 8; ks2++) {
            float e0 = __expf(acc[2 * ks2][0] * SCALE);
            float e1 = __expf(acc[2 * ks2][1] * SCALE);
            float e2 = __expf(acc[2 * ks2][2] * SCALE);
            float e3 = __expf(acc[2 * ks2][3] * SCALE);
            float e4 = __expf(acc[2 * ks2 + 1][0] * SCALE);
            float e5 = __expf(acc[2 * ks2 + 1][1] * SCALE);
            float e6 = __expf(acc[2 * ks2 + 1][2] * SCALE);
            float e7 = __expf(acc[2 * ks2 + 1][3] * SCALE);
            uint4 ah, al;
            ah.x = prmt_hi(__float_as_uint(e0), __float_as_uint(e1));
            ah.y = prmt_hi(__float_as_uint(e2), __float_as_uint(e3));
            ah.z = prmt_hi(__float_as_uint(e4), __float_as_uint(e5));
            ah.w = prmt_hi(__float_as_uint(e6), __float_as_uint(e7));
            al.x = bf16x2_rn(e1 - truncb(e1), e0 - truncb(e0));
            al.y = bf16x2_rn(e3 - truncb(e3), e2 - truncb(e2));
            al.z = bf16x2_rn(e5 - truncb(e5), e4 - truncb(e4));
            al.w = bf16x2_rn(e7 - truncb(e7), e6 - truncb(e6));
#pragma unroll
            for (int nt = 0; nt < 8; nt++) {
                uint2 bh = ldB16<8>(Vh, ks2, nt, lane);
                uint2 bl = ldB16<8>(Vl, ks2, nt, lane);
                mma16(o[nt], ah, bh);
                mma16(o[nt], ah, bl);
                mma16(o[nt], al, bh);
            }
        }

        if (hn) {
            CP_WAIT0();
            __syncthreads();   // packs consumed by all + staged data visible
            k2_convert(SK, SV, linv_s, k0n, Kp, Vh, Vl, rb, c4, lane);
            __syncthreads();   // packs ready
        }
    }

    int r = lane >> 2, c2 = (lane & 3) << 1;
    float* obase = g_att + ((size_t)b * SEQ + q0 + 16 * w + r) * DIM + h * HD;
#pragma unroll
    for (int nt = 0; nt < 8; nt++) {
        *(float2*)(obase + nt * 8 + c2) = make_float2(o[nt][0], o[nt][1]);
        *(float2*)(obase + (size_t)8 * DIM + nt * 8 + c2) =
            make_float2(o[nt][2], o[nt][3]);
    }
}

// ---------------------------------------------------------------------------
// Kernel 3: out = g_att @ W^T + b.  bf16 3-pass split. (unchanged)
// ---------------------------------------------------------------------------
__global__ void __launch_bounds__(256, 2) k3_linear(const float* __restrict__ Wg,
                                                    const float* __restrict__ bg,
                                                    float* __restrict__ Og) {
    extern __shared__ u32 smu[];
    u32* Xh = smu;             // 4096
    u32* Xl = smu + 4096;      // 4096
    u32* Wh = smu + 8192;      // 4224
    u32* Wl = smu + 12416;     // 4224

    int tid = threadIdx.x, lane = tid & 31, w = tid >> 5;
    int wm = w >> 2, wn = w & 3;
    int n0 = blockIdx.x << 7, m0 = blockIdx.y << 7;

    float acc[4][4][4];
#pragma unroll
    for (int i = 0; i < 4; i++)
#pragma unroll
        for (int j = 0; j < 4; j++)
#pragma unroll
            for (int t = 0; t < 4; t++) acc[i][j][t] = 0.f;

    int rb = tid >> 4, c4 = (tid & 15) << 2;
    for (int d0 = 0; d0 < DIM; d0 += 64) {
        __syncthreads();
#pragma unroll
        for (int it = 0; it < 8; it++) {
            int r = rb + (it << 4);
            float4 x = *(const float4*)(g_att + (size_t)(m0 + r) * DIM + d0 + c4);
            float4 wv = *(const float4*)(Wg + (size_t)(n0 + r) * DIM + d0 + c4);
            const float* xf = &x.x; const float* wf = &wv.x;
            int ks = c4 >> 4, kkb = c4 & 15;
#pragma unroll
            for (int p = 0; p < 2; p++) {
                int kk = kkb + 2 * p;
                int c = (kk & 7) >> 1;
                {
                    int slot = ((r >> 3) & 1) | ((kk >> 3) << 1);
                    int idx = ((ks * 8 + (r >> 4)) * 32 + ((r & 7) << 2) + c) * 4 + slot;
                    float a = xf[2 * p], bb = xf[2 * p + 1];
                    Xh[idx] = prmt_hi(__float_as_uint(a), __float_as_uint(bb));
                    Xl[idx] = bf16x2_rn(bb - truncb(bb), a - truncb(a));
                }
                {
                    int breg = kk >> 3;
                    int idx = ((ks * 16 + (r >> 3)) * 33 + ((r & 7) << 2) + c) * 2 + breg;
                    float a = wf[2 * p], bb = wf[2 * p + 1];
                    Wh[idx] = prmt_hi(__float_as_uint(a), __float_as_uint(bb));
                    Wl[idx] = bf16x2_rn(bb - truncb(bb), a - truncb(a));
                }
            }
        }
        __syncthreads();

#pragma unroll
        for (int ks = 0; ks < 4; ks++) {
            uint4 ah[4], al[4]; uint2 bh[4], bl[4];
#pragma unroll
            for (int i = 0; i < 4; i++) {
                ah[i] = ldA16(Xh, ks, wm * 4 + i, lane);
                al[i] = ldA16(Xl, ks, wm * 4 + i, lane);
            }
#pragma unroll
            for (int j = 0; j < 4; j++) {
                bh[j] = ldB16<16>(Wh, ks, wn * 4 + j, lane);
                bl[j] = ldB16<16>(Wl, ks, wn * 4 + j, lane);
            }
#pragma unroll
            for (int i = 0; i < 4; i++)
#pragma unroll
                for (int j = 0; j < 4; j++) {
                    mma16(acc[i][j], ah[i], bh[j]);
                    mma16(acc[i][j], ah[i], bl[j]);
                    mma16(acc[i][j], al[i], bh[j]);
                }
        }
    }

#pragma unroll
    for (int i = 0; i < 4; i++)
#pragma unroll
        for (int j = 0; j < 4; j++) {
            int r = wm * 64 + i * 16 + (lane >> 2);
            int n = wn * 32 + j * 8 + ((lane & 3) << 1);
            float2 bb = *(const float2*)(bg + n0 + n);
            float* p = Og + (size_t)(m0 + r) * DIM + n0 + n;
            *(float2*)p = make_float2(acc[i][j][0] + bb.x, acc[i][j][1] + bb.y);
            *(float2*)(p + (size_t)8 * DIM) =
                make_float2(acc[i][j][2] + bb.x, acc[i][j][3] + bb.y);
        }
}

// ---------------------------------------------------------------------------

extern "C" void kernel_launch(void* const* d_in, const int* in_sizes, int n_in,
                              void* d_out, int out_size) {
    const float* Q = (const float*)d_in[0];
    const float* K = (const float*)d_in[1];
    const float* V = (const float*)d_in[2];
    const float* W = (const float*)d_in[3];
    const float* bias = (const float*)d_in[4];
    float* out = (float*)d_out;
    (void)in_sizes; (void)n_in; (void)out_size;

    const int smem1 = (4096 + 4224 + 128) * 4;   // 33792
    const int smem2 = 43264 * 4;                 // 173056
    const int smem3 = 16640 * 4;                 // 66560

    cudaFuncSetAttribute(k1_colsum, cudaFuncAttributeMaxDynamicSharedMemorySize, smem1);
    cudaFuncSetAttribute(k2_attnv,  cudaFuncAttributeMaxDynamicSharedMemorySize, smem2);
    cudaFuncSetAttribute(k3_linear, cudaFuncAttributeMaxDynamicSharedMemorySize, smem3);

    dim3 gAttn(SEQ / 128, NH, NB);          // 1024 CTAs
    k1_colsum<<<gAttn, 256, smem1>>>(Q, K);
    k2_attnv<<<gAttn, 256, smem2>>>(Q, K, V);

    dim3 gLin(DIM / 128, (NB * SEQ) / 128); // 512 CTAs
    k3_linear<<<gLin, 256, smem3>>>(W, bias, out);
}

// round 8
// speedup vs baseline: 1.2004x; 1.2004x over previous
#include <cuda_runtime.h>

#define NB 4
#define NH 16
#define SEQ 2048
#define DIM 1024
#define HD 64
#define SCALE 0.03125f   // 1/sqrt(1024)

typedef unsigned int u32;

// Scratch (allocation-free rule: __device__ globals)
__device__ float g_linv[NB * NH * SEQ];
__device__ float g_att[(size_t)NB * SEQ * DIM];

// ---------------------------------------------------------------------------
// Low-level helpers (portable sm_80+ PTX)
// ---------------------------------------------------------------------------
__device__ __forceinline__ u32 f2tf(float x) {
    u32 r; asm("cvt.rna.tf32.f32 %0, %1;" : "=r"(r) : "f"(x)); return r;
}
__device__ __forceinline__ u32 prmt_hi(u32 a, u32 b) {   // {lo16=a.hi16, hi16=b.hi16}
    u32 r; asm("prmt.b32 %0, %1, %2, 0x7632;" : "=r"(r) : "r"(a), "r"(b)); return r;
}
__device__ __forceinline__ u32 bf16x2_rn(float hi, float lo) {
    u32 r; asm("cvt.rn.bf16x2.f32 %0, %1, %2;" : "=r"(r) : "f"(hi), "f"(lo)); return r;
}
__device__ __forceinline__ float truncb(float x) {       // exact bf16 truncation
    return __uint_as_float(__float_as_uint(x) & 0xFFFF0000u);
}

// m16n8k8 tf32 mma
__device__ __forceinline__ void mma8(float c[4], uint4 a, uint2 b) {
    asm volatile(
        "mma.sync.aligned.m16n8k8.row.col.f32.tf32.tf32.f32 "
        "{%0,%1,%2,%3}, {%4,%5,%6,%7}, {%8,%9}, {%0,%1,%2,%3};"
        : "+f"(c[0]), "+f"(c[1]), "+f"(c[2]), "+f"(c[3])
        : "r"(a.x), "r"(a.y), "r"(a.z), "r"(a.w), "r"(b.x), "r"(b.y));
}
// m16n8k16 bf16 mma
__device__ __forceinline__ void mma16(float c[4], uint4 a, uint2 b) {
    asm volatile(
        "mma.sync.aligned.m16n8k16.row.col.f32.bf16.bf16.f32 "
        "{%0,%1,%2,%3}, {%4,%5,%6,%7}, {%8,%9}, {%0,%1,%2,%3};"
        : "+f"(c[0]), "+f"(c[1]), "+f"(c[2]), "+f"(c[3])
        : "r"(a.x), "r"(a.y), "r"(a.z), "r"(a.w), "r"(b.x), "r"(b.y));
}

// ---------------------------------------------------------------------------
// tf32 fragment packs
// A-pack: [ks][mt][lane] uint4; B-pack: [ks][nt][lane] uint2
// ---------------------------------------------------------------------------
template<int MT>
__device__ __forceinline__ uint4 ldAf(const u32* A, int ks, int mt, int lane) {
    return *(const uint4*)(A + ((size_t)((ks * MT + mt) * 32 + lane)) * 4);
}
template<int NT>
__device__ __forceinline__ uint2 ldBf(const u32* B, int ks, int nt, int lane) {
    return *(const uint2*)(B + ((size_t)((ks * NT + nt) * 32 + lane)) * 2);
}
template<int MT>
__device__ __forceinline__ void stA4(u32* A, int r, int c4, float4 v) {
    int base = (((c4 >> 3) * MT + (r >> 4)) * 32 + ((r & 7) << 2)) * 4
             + (((r >> 3) & 1) | (((c4 >> 2) & 1) << 1));
    A[base + 0]  = f2tf(v.x);
    A[base + 4]  = f2tf(v.y);
    A[base + 8]  = f2tf(v.z);
    A[base + 12] = f2tf(v.w);
}
template<int NT>
__device__ __forceinline__ void stB4_nk(u32* B, int n, int c4, float4 v) {
    int base = (((c4 >> 3) * NT + (n >> 3)) * 32 + ((n & 7) << 2)) * 2
             + ((c4 >> 2) & 1);
    B[base + 0] = f2tf(v.x);
    B[base + 2] = f2tf(v.y);
    B[base + 4] = f2tf(v.z);
    B[base + 6] = f2tf(v.w);
}

// ---------------------------------------------------------------------------
// bf16 fragment packs (m16n8k16).  B-pack padded: stride 33 lane-pairs.
// ---------------------------------------------------------------------------
__device__ __forceinline__ uint4 ldA16(const u32* A, int ks, int mt, int lane) {
    return *(const uint4*)(A + ((size_t)((ks * 8 + mt) * 32 + lane)) * 4);
}
template<int NT>
__device__ __forceinline__ uint2 ldB16(const u32* B, int ks, int nt, int lane) {
    return *(const uint2*)(B + ((size_t)((ks * NT + nt) * 33 + lane)) * 2);
}
__device__ __forceinline__ void stA16_rn(u32* A, int r, int c4, float4 v) {
    int ks = c4 >> 4, kkb = c4 & 15;
    const float* f = &v.x;
#pragma unroll
    for (int p = 0; p < 2; p++) {
        int kk = kkb + 2 * p;
        int c = (kk & 7) >> 1, slot = ((r >> 3) & 1) | ((kk >> 3) << 1);
        int idx = ((ks * 8 + (r >> 4)) * 32 + ((r & 7) << 2) + c) * 4 + slot;
        A[idx] = bf16x2_rn(f[2 * p + 1], f[2 * p]);
    }
}
template<int NT>
__device__ __forceinline__ void stB16_rn(u32* B, int n, int c4, float4 v) {
    int ks = c4 >> 4, kkb = c4 & 15;
    const float* f = &v.x;
#pragma unroll
    for (int p = 0; p < 2; p++) {
        int kk = kkb + 2 * p;
        int c = (kk & 7) >> 1, breg = kk >> 3;
        int idx = ((ks * NT + (n >> 3)) * 33 + ((n & 7) << 2) + c) * 2 + breg;
        B[idx] = bf16x2_rn(f[2 * p + 1], f[2 * p]);
    }
}

// ---------------------------------------------------------------------------
// Kernel 1: l[k] = sum_q exp(s[q,k]); store 1/l. (unchanged — proven)
// ---------------------------------------------------------------------------
__global__ void __launch_bounds__(256) k1_colsum(const float* __restrict__ Qg,
                                                 const float* __restrict__ Kg) {
    extern __shared__ u32 smu[];
    u32* Ka = smu;                       // 4096 u32
    u32* Qb = smu + 4096;                // 4224 u32
    float* colsum = (float*)(smu + 8320);
    int tid = threadIdx.x, lane = tid & 31, w = tid >> 5;
    int wm = w >> 2, wn = w & 3;
    int b = blockIdx.z, h = blockIdx.y, k0 = blockIdx.x << 7;

    const float* Kb = Kg + ((size_t)b * SEQ + k0) * DIM + h * HD;
    const float* Qbase = Qg + (size_t)b * SEQ * DIM + h * HD;

    int rb = tid >> 4, c4 = (tid & 15) << 2;
#pragma unroll
    for (int it = 0; it < 8; it++) {
        int r = rb + (it << 4);
        stA16_rn(Ka, r, c4, *(const float4*)(Kb + (size_t)r * DIM + c4));
    }
    if (tid < 128) colsum[tid] = 0.f;

    float sume[4][2];
#pragma unroll
    for (int i = 0; i < 4; i++) { sume[i][0] = 0.f; sume[i][1] = 0.f; }

    for (int q0 = 0; q0 < SEQ; q0 += 128) {
        __syncthreads();
#pragma unroll
        for (int it = 0; it < 8; it++) {
            int n = rb + (it << 4);
            stB16_rn<16>(Qb, n, c4,
                         *(const float4*)(Qbase + (size_t)(q0 + n) * DIM + c4));
        }
        __syncthreads();

        float acc[4][4][4];
#pragma unroll
        for (int i = 0; i < 4; i++)
#pragma unroll
            for (int j = 0; j < 4; j++)
#pragma unroll
                for (int t = 0; t < 4; t++) acc[i][j][t] = 0.f;

#pragma unroll
        for (int ks = 0; ks < 4; ks++) {
            uint4 af[4]; uint2 bf[4];
#pragma unroll
            for (int i = 0; i < 4; i++) af[i] = ldA16(Ka, ks, wm * 4 + i, lane);
#pragma unroll
            for (int j = 0; j < 4; j++) bf[j] = ldB16<16>(Qb, ks, wn * 4 + j, lane);
#pragma unroll
            for (int i = 0; i < 4; i++)
#pragma unroll
                for (int j = 0; j < 4; j++) mma16(acc[i][j], af[i], bf[j]);
        }
#pragma unroll
        for (int i = 0; i < 4; i++)
#pragma unroll
            for (int j = 0; j < 4; j++) {
                sume[i][0] += __expf(acc[i][j][0] * SCALE) + __expf(acc[i][j][1] * SCALE);
                sume[i][1] += __expf(acc[i][j][2] * SCALE) + __expf(acc[i][j][3] * SCALE);
            }
    }

#pragma unroll
    for (int i = 0; i < 4; i++)
#pragma unroll
        for (int hh = 0; hh < 2; hh++) {
            float v = sume[i][hh];
            v += __shfl_xor_sync(0xffffffffu, v, 1);
            v += __shfl_xor_sync(0xffffffffu, v, 2);
            if ((lane & 3) == 0)
                atomicAdd(&colsum[wm * 64 + i * 16 + (lane >> 2) + hh * 8], v);
        }
    __syncthreads();
    if (tid < 128)
        g_linv[((size_t)b * NH + h) * SEQ + k0 + tid] = 1.0f / colsum[tid];
}

// ---------------------------------------------------------------------------
// Kernel 2: out[q,:] = sum_k exp(s[q,k]) * (linv[k]*v[k,:]).
// r5 structure, but gemm1 processes the 128-k tile in TWO 64-col halves so
// peak accumulator registers halve (acc[8][4] instead of [16][4]) ->
// fits 128 regs -> __launch_bounds__(256,2) gives 2 CTAs/SM; cross-CTA
// overlap hides convert/sync/LDG bubbles. Same mma ops & order as r5.
// ---------------------------------------------------------------------------
__global__ void __launch_bounds__(256, 2) k2_attnv(const float* __restrict__ Qg,
                                                   const float* __restrict__ Kg,
                                                   const float* __restrict__ Vg) {
    extern __shared__ u32 smu[];
    u32* Qa = smu;             // tf32 A-pack 128q x 64d : 8192
    u32* Kp = smu + 8192;      // tf32 B-pack 128k x 64d : 8192
    u32* Vh = smu + 16384;     // bf16 B-pack 128k x 64d : 4224 (padded)
    u32* Vl = smu + 20608;     // bf16 B-pack            : 4224
    // total 24832 u32 = 99328 B  (2 CTAs/SM fit in 228KB)

    int tid = threadIdx.x, lane = tid & 31, w = tid >> 5;
    int b = blockIdx.z, h = blockIdx.y, q0 = blockIdx.x << 7;

    const float* Qb = Qg + ((size_t)b * SEQ + q0) * DIM + h * HD;
    const float* Kbase = Kg + (size_t)b * SEQ * DIM + h * HD;
    const float* Vbase = Vg + (size_t)b * SEQ * DIM + h * HD;
    const float* linv = g_linv + ((size_t)b * NH + h) * SEQ;

    int rb = tid >> 4, c4 = (tid & 15) << 2;
#pragma unroll
    for (int it = 0; it < 8; it++) {
        int r = rb + (it << 4);
        stA4<8>(Qa, r, c4, *(const float4*)(Qb + (size_t)r * DIM + c4));
    }

    float o[8][4];
#pragma unroll
    for (int nt = 0; nt < 8; nt++)
#pragma unroll
        for (int t = 0; t < 4; t++) o[nt][t] = 0.f;

    for (int k0 = 0; k0 < SEQ; k0 += 128) {
        __syncthreads();   // previous tile fully consumed
        // K tile -> tf32 B-pack
#pragma unroll
        for (int it = 0; it < 8; it++) {
            int n = rb + (it << 4);
            stB4_nk<16>(Kp, n, c4,
                        *(const float4*)(Kbase + (size_t)(k0 + n) * DIM + c4));
        }
        // V' tile -> bf16 hi/lo B-packs (pair exchange via shfl)
#pragma unroll
        for (int it = 0; it < 8; it++) {
            int kt = rb + (it << 4);
            float rl = __ldg(linv + k0 + kt);
            float4 v = *(const float4*)(Vbase + (size_t)(k0 + kt) * DIM + c4);
            v.x *= rl; v.y *= rl; v.z *= rl; v.w *= rl;
            float4 oth;
            oth.x = __shfl_xor_sync(0xffffffffu, v.x, 16);
            oth.y = __shfl_xor_sync(0xffffffffu, v.y, 16);
            oth.z = __shfl_xor_sync(0xffffffffu, v.z, 16);
            oth.w = __shfl_xor_sync(0xffffffffu, v.w, 16);
            float4 ve, vo;
            if (lane & 16) { ve = oth; vo = v; } else { ve = v; vo = oth; }
            int ke = kt & ~1;
            int ksv = ke >> 4, kk = ke & 15;
            int c = (kk & 7) >> 1, breg = kk >> 3;
            const float* pe = &ve.x; const float* po = &vo.x;
#pragma unroll
            for (int j = 0; j < 4; j++) {
                int d = c4 + j;
                int idx = ((ksv * 8 + (d >> 3)) * 33 + ((d & 7) << 2) + c) * 2 + breg;
                float a = pe[j], bb = po[j];
                if (!(lane & 16))
                    Vh[idx] = prmt_hi(__float_as_uint(a), __float_as_uint(bb));
                else
                    Vl[idx] = bf16x2_rn(bb - truncb(bb), a - truncb(a));
            }
        }
        __syncthreads();

        // two k-halves of 64 cols each: gemm1 half -> exp -> gemm2 half
#pragma unroll
        for (int half = 0; half < 2; half++) {
            float acc[8][4];
#pragma unroll
            for (int nt = 0; nt < 8; nt++)
#pragma unroll
                for (int tt = 0; tt < 4; tt++) acc[nt][tt] = 0.f;
#pragma unroll
            for (int ks = 0; ks < 8; ks++) {
                uint4 a = ldAf<8>(Qa, ks, w, lane);
#pragma unroll
                for (int nt = 0; nt < 8; nt++) {
                    uint2 bf = ldBf<16>(Kp, ks, half * 8 + nt, lane);
                    mma8(acc[nt], a, bf);
                }
            }

#pragma unroll
            for (int j2 = 0; j2 < 4; j2++) {
                float e0 = __expf(acc[2 * j2][0] * SCALE);
                float e1 = __expf(acc[2 * j2][1] * SCALE);
                float e2 = __expf(acc[2 * j2][2] * SCALE);
                float e3 = __expf(acc[2 * j2][3] * SCALE);
                float e4 = __expf(acc[2 * j2 + 1][0] * SCALE);
                float e5 = __expf(acc[2 * j2 + 1][1] * SCALE);
                float e6 = __expf(acc[2 * j2 + 1][2] * SCALE);
                float e7 = __expf(acc[2 * j2 + 1][3] * SCALE);
                uint4 ah, al;
                ah.x = prmt_hi(__float_as_uint(e0), __float_as_uint(e1));
                ah.y = prmt_hi(__float_as_uint(e2), __float_as_uint(e3));
                ah.z = prmt_hi(__float_as_uint(e4), __float_as_uint(e5));
                ah.w = prmt_hi(__float_as_uint(e6), __float_as_uint(e7));
                al.x = bf16x2_rn(e1 - truncb(e1), e0 - truncb(e0));
                al.y = bf16x2_rn(e3 - truncb(e3), e2 - truncb(e2));
                al.z = bf16x2_rn(e5 - truncb(e5), e4 - truncb(e4));
                al.w = bf16x2_rn(e7 - truncb(e7), e6 - truncb(e6));
                int ks2 = half * 4 + j2;
#pragma unroll
                for (int nt = 0; nt < 8; nt++) {
                    uint2 bh = ldB16<8>(Vh, ks2, nt, lane);
                    uint2 bl = ldB16<8>(Vl, ks2, nt, lane);
                    mma16(o[nt], ah, bh);
                    mma16(o[nt], ah, bl);
                    mma16(o[nt], al, bh);
                }
            }
        }
    }

    int r = lane >> 2, c2 = (lane & 3) << 1;
    float* obase = g_att + ((size_t)b * SEQ + q0 + 16 * w + r) * DIM + h * HD;
#pragma unroll
    for (int nt = 0; nt < 8; nt++) {
        *(float2*)(obase + nt * 8 + c2) = make_float2(o[nt][0], o[nt][1]);
        *(float2*)(obase + (size_t)8 * DIM + nt * 8 + c2) =
            make_float2(o[nt][2], o[nt][3]);
    }
}

// ---------------------------------------------------------------------------
// Kernel 3: out = g_att @ W^T + b.  bf16 3-pass split. (unchanged)
// ---------------------------------------------------------------------------
__global__ void __launch_bounds__(256, 2) k3_linear(const float* __restrict__ Wg,
                                                    const float* __restrict__ bg,
                                                    float* __restrict__ Og) {
    extern __shared__ u32 smu[];
    u32* Xh = smu;             // 4096
    u32* Xl = smu + 4096;      // 4096
    u32* Wh = smu + 8192;      // 4224
    u32* Wl = smu + 12416;     // 4224

    int tid = threadIdx.x, lane = tid & 31, w = tid >> 5;
    int wm = w >> 2, wn = w & 3;
    int n0 = blockIdx.x << 7, m0 = blockIdx.y << 7;

    float acc[4][4][4];
#pragma unroll
    for (int i = 0; i < 4; i++)
#pragma unroll
        for (int j = 0; j < 4; j++)
#pragma unroll
            for (int t = 0; t < 4; t++) acc[i][j][t] = 0.f;

    int rb = tid >> 4, c4 = (tid & 15) << 2;
    for (int d0 = 0; d0 < DIM; d0 += 64) {
        __syncthreads();
#pragma unroll
        for (int it = 0; it < 8; it++) {
            int r = rb + (it << 4);
            float4 x = *(const float4*)(g_att + (size_t)(m0 + r) * DIM + d0 + c4);
            float4 wv = *(const float4*)(Wg + (size_t)(n0 + r) * DIM + d0 + c4);
            const float* xf = &x.x; const float* wf = &wv.x;
            int ks = c4 >> 4, kkb = c4 & 15;
#pragma unroll
            for (int p = 0; p < 2; p++) {
                int kk = kkb + 2 * p;
                int c = (kk & 7) >> 1;
                {
                    int slot = ((r >> 3) & 1) | ((kk >> 3) << 1);
                    int idx = ((ks * 8 + (r >> 4)) * 32 + ((r & 7) << 2) + c) * 4 + slot;
                    float a = xf[2 * p], bb = xf[2 * p + 1];
                    Xh[idx] = prmt_hi(__float_as_uint(a), __float_as_uint(bb));
                    Xl[idx] = bf16x2_rn(bb - truncb(bb), a - truncb(a));
                }
                {
                    int breg = kk >> 3;
                    int idx = ((ks * 16 + (r >> 3)) * 33 + ((r & 7) << 2) + c) * 2 + breg;
                    float a = wf[2 * p], bb = wf[2 * p + 1];
                    Wh[idx] = prmt_hi(__float_as_uint(a), __float_as_uint(bb));
                    Wl[idx] = bf16x2_rn(bb - truncb(bb), a - truncb(a));
                }
            }
        }
        __syncthreads();

#pragma unroll
        for (int ks = 0; ks < 4; ks++) {
            uint4 ah[4], al[4]; uint2 bh[4], bl[4];
#pragma unroll
            for (int i = 0; i < 4; i++) {
                ah[i] = ldA16(Xh, ks, wm * 4 + i, lane);
                al[i] = ldA16(Xl, ks, wm * 4 + i, lane);
            }
#pragma unroll
            for (int j = 0; j < 4; j++) {
                bh[j] = ldB16<16>(Wh, ks, wn * 4 + j, lane);
                bl[j] = ldB16<16>(Wl, ks, wn * 4 + j, lane);
            }
#pragma unroll
            for (int i = 0; i < 4; i++)
#pragma unroll
                for (int j = 0; j < 4; j++) {
                    mma16(acc[i][j], ah[i], bh[j]);
                    mma16(acc[i][j], ah[i], bl[j]);
                    mma16(acc[i][j], al[i], bh[j]);
                }
        }
    }

#pragma unroll
    for (int i = 0; i < 4; i++)
#pragma unroll
        for (int j = 0; j < 4; j++) {
            int r = wm * 64 + i * 16 + (lane >> 2);
            int n = wn * 32 + j * 8 + ((lane & 3) << 1);
            float2 bb = *(const float2*)(bg + n0 + n);
            float* p = Og + (size_t)(m0 + r) * DIM + n0 + n;
            *(float2*)p = make_float2(acc[i][j][0] + bb.x, acc[i][j][1] + bb.y);
            *(float2*)(p + (size_t)8 * DIM) =
                make_float2(acc[i][j][2] + bb.x, acc[i][j][3] + bb.y);
        }
}

// ---------------------------------------------------------------------------

extern "C" void kernel_launch(void* const* d_in, const int* in_sizes, int n_in,
                              void* d_out, int out_size) {
    const float* Q = (const float*)d_in[0];
    const float* K = (const float*)d_in[1];
    const float* V = (const float*)d_in[2];
    const float* W = (const float*)d_in[3];
    const float* bias = (const float*)d_in[4];
    float* out = (float*)d_out;
    (void)in_sizes; (void)n_in; (void)out_size;

    const int smem1 = (4096 + 4224 + 128) * 4;   // 33792
    const int smem2 = 24832 * 4;                 // 99328
    const int smem3 = 16640 * 4;                 // 66560

    cudaFuncSetAttribute(k1_colsum, cudaFuncAttributeMaxDynamicSharedMemorySize, smem1);
    cudaFuncSetAttribute(k2_attnv,  cudaFuncAttributeMaxDynamicSharedMemorySize, smem2);
    cudaFuncSetAttribute(k3_linear, cudaFuncAttributeMaxDynamicSharedMemorySize, smem3);

    dim3 gAttn(SEQ / 128, NH, NB);          // 1024 CTAs
    k1_colsum<<<gAttn, 256, smem1>>>(Q, K);
    k2_attnv<<<gAttn, 256, smem2>>>(Q, K, V);

    dim3 gLin(DIM / 128, (NB * SEQ) / 128); // 512 CTAs
    k3_linear<<<gLin, 256, smem3>>>(W, bias, out);
}

// round 11
// speedup vs baseline: 1.7538x; 1.4610x over previous
#include <cuda_runtime.h>

#define NB 4
#define NH 16
#define SEQ 2048
#define DIM 1024
#define HD 64
#define SCALE 0.03125f   // 1/sqrt(1024)

typedef unsigned int u32;

// Scratch (allocation-free rule: __device__ globals)
__device__ float g_linv[NB * NH * SEQ];
__device__ float g_att[(size_t)NB * SEQ * DIM];

// ---------------------------------------------------------------------------
// Low-level helpers (portable sm_80+ PTX)
// ---------------------------------------------------------------------------
__device__ __forceinline__ u32 bf16x2_rn(float hi, float lo) {
    u32 r; asm("cvt.rn.bf16x2.f32 %0, %1, %2;" : "=r"(r) : "f"(hi), "f"(lo)); return r;
}
__device__ __forceinline__ u32 f16x2_rn(float hi, float lo) {
    u32 r; asm("cvt.rn.f16x2.f32 %0, %1, %2;" : "=r"(r) : "f"(hi), "f"(lo)); return r;
}
__device__ __forceinline__ u32 prmt_hi(u32 a, u32 b) {   // {lo16=a.hi16, hi16=b.hi16}
    u32 r; asm("prmt.b32 %0, %1, %2, 0x7632;" : "=r"(r) : "r"(a), "r"(b)); return r;
}
__device__ __forceinline__ float truncb(float x) {       // exact bf16 truncation
    return __uint_as_float(__float_as_uint(x) & 0xFFFF0000u);
}

// m16n8k16 bf16 mma
__device__ __forceinline__ void mma16(float c[4], uint4 a, uint2 b) {
    asm volatile(
        "mma.sync.aligned.m16n8k16.row.col.f32.bf16.bf16.f32 "
        "{%0,%1,%2,%3}, {%4,%5,%6,%7}, {%8,%9}, {%0,%1,%2,%3};"
        : "+f"(c[0]), "+f"(c[1]), "+f"(c[2]), "+f"(c[3])
        : "r"(a.x), "r"(a.y), "r"(a.z), "r"(a.w), "r"(b.x), "r"(b.y));
}
// m16n8k16 fp16 mma
__device__ __forceinline__ void mma16f(float c[4], uint4 a, uint2 b) {
    asm volatile(
        "mma.sync.aligned.m16n8k16.row.col.f32.f16.f16.f32 "
        "{%0,%1,%2,%3}, {%4,%5,%6,%7}, {%8,%9}, {%0,%1,%2,%3};"
        : "+f"(c[0]), "+f"(c[1]), "+f"(c[2]), "+f"(c[3])
        : "r"(a.x), "r"(a.y), "r"(a.z), "r"(a.w), "r"(b.x), "r"(b.y));
}

// ---------------------------------------------------------------------------
// 16-bit fragment packs (m16n8k16). A-pack: [ks][mt(8)][lane] uint4.
// B-pack padded: [ks][nt][33 lane-pairs] uint2.
// ---------------------------------------------------------------------------
__device__ __forceinline__ uint4 ldA16(const u32* A, int ks, int mt, int lane) {
    return *(const uint4*)(A + ((size_t)((ks * 8 + mt) * 32 + lane)) * 4);
}
template<int NT>
__device__ __forceinline__ uint2 ldB16(const u32* B, int ks, int nt, int lane) {
    return *(const uint2*)(B + ((size_t)((ks * NT + nt) * 33 + lane)) * 2);
}
// bf16 stores (k1/k3)
__device__ __forceinline__ void stA16_rn(u32* A, int r, int c4, float4 v) {
    int ks = c4 >> 4, kkb = c4 & 15;
    const float* f = &v.x;
#pragma unroll
    for (int p = 0; p < 2; p++) {
        int kk = kkb + 2 * p;
        int c = (kk & 7) >> 1, slot = ((r >> 3) & 1) | ((kk >> 3) << 1);
        int idx = ((ks * 8 + (r >> 4)) * 32 + ((r & 7) << 2) + c) * 4 + slot;
        A[idx] = bf16x2_rn(f[2 * p + 1], f[2 * p]);
    }
}
template<int NT>
__device__ __forceinline__ void stB16_rn(u32* B, int n, int c4, float4 v) {
    int ks = c4 >> 4, kkb = c4 & 15;
    const float* f = &v.x;
#pragma unroll
    for (int p = 0; p < 2; p++) {
        int kk = kkb + 2 * p;
        int c = (kk & 7) >> 1, breg = kk >> 3;
        int idx = ((ks * NT + (n >> 3)) * 33 + ((n & 7) << 2) + c) * 2 + breg;
        B[idx] = bf16x2_rn(f[2 * p + 1], f[2 * p]);
    }
}
// fp16 stores (k2)
__device__ __forceinline__ void stA16f(u32* A, int r, int c4, float4 v) {
    int ks = c4 >> 4, kkb = c4 & 15;
    const float* f = &v.x;
#pragma unroll
    for (int p = 0; p < 2; p++) {
        int kk = kkb + 2 * p;
        int c = (kk & 7) >> 1, slot = ((r >> 3) & 1) | ((kk >> 3) << 1);
        int idx = ((ks * 8 + (r >> 4)) * 32 + ((r & 7) << 2) + c) * 4 + slot;
        A[idx] = f16x2_rn(f[2 * p + 1], f[2 * p]);
    }
}
template<int NT>
__device__ __forceinline__ void stB16f(u32* B, int n, int c4, float4 v) {
    int ks = c4 >> 4, kkb = c4 & 15;
    const float* f = &v.x;
#pragma unroll
    for (int p = 0; p < 2; p++) {
        int kk = kkb + 2 * p;
        int c = (kk & 7) >> 1, breg = kk >> 3;
        int idx = ((ks * NT + (n >> 3)) * 33 + ((n & 7) << 2) + c) * 2 + breg;
        B[idx] = f16x2_rn(f[2 * p + 1], f[2 * p]);
    }
}

// ---------------------------------------------------------------------------
// Kernel 1: l[k] = sum_q exp(s[q,k]); store 1/l. (unchanged — proven)
// ---------------------------------------------------------------------------
__global__ void __launch_bounds__(256) k1_colsum(const float* __restrict__ Qg,
                                                 const float* __restrict__ Kg) {
    extern __shared__ u32 smu[];
    u32* Ka = smu;                       // 4096 u32
    u32* Qb = smu + 4096;                // 4224 u32
    float* colsum = (float*)(smu + 8320);
    int tid = threadIdx.x, lane = tid & 31, w = tid >> 5;
    int wm = w >> 2, wn = w & 3;
    int b = blockIdx.z, h = blockIdx.y, k0 = blockIdx.x << 7;

    const float* Kb = Kg + ((size_t)b * SEQ + k0) * DIM + h * HD;
    const float* Qbase = Qg + (size_t)b * SEQ * DIM + h * HD;

    int rb = tid >> 4, c4 = (tid & 15) << 2;
#pragma unroll
    for (int it = 0; it < 8; it++) {
        int r = rb + (it << 4);
        stA16_rn(Ka, r, c4, *(const float4*)(Kb + (size_t)r * DIM + c4));
    }
    if (tid < 128) colsum[tid] = 0.f;

    float sume[4][2];
#pragma unroll
    for (int i = 0; i < 4; i++) { sume[i][0] = 0.f; sume[i][1] = 0.f; }

    for (int q0 = 0; q0 < SEQ; q0 += 128) {
        __syncthreads();
#pragma unroll
        for (int it = 0; it < 8; it++) {
            int n = rb + (it << 4);
            stB16_rn<16>(Qb, n, c4,
                         *(const float4*)(Qbase + (size_t)(q0 + n) * DIM + c4));
        }
        __syncthreads();

        float acc[4][4][4];
#pragma unroll
        for (int i = 0; i < 4; i++)
#pragma unroll
            for (int j = 0; j < 4; j++)
#pragma unroll
                for (int t = 0; t < 4; t++) acc[i][j][t] = 0.f;

#pragma unroll
        for (int ks = 0; ks < 4; ks++) {
            uint4 af[4]; uint2 bf[4];
#pragma unroll
            for (int i = 0; i < 4; i++) af[i] = ldA16(Ka, ks, wm * 4 + i, lane);
#pragma unroll
            for (int j = 0; j < 4; j++) bf[j] = ldB16<16>(Qb, ks, wn * 4 + j, lane);
#pragma unroll
            for (int i = 0; i < 4; i++)
#pragma unroll
                for (int j = 0; j < 4; j++) mma16(acc[i][j], af[i], bf[j]);
        }
#pragma unroll
        for (int i = 0; i < 4; i++)
#pragma unroll
            for (int j = 0; j < 4; j++) {
                sume[i][0] += __expf(acc[i][j][0] * SCALE) + __expf(acc[i][j][1] * SCALE);
                sume[i][1] += __expf(acc[i][j][2] * SCALE) + __expf(acc[i][j][3] * SCALE);
            }
    }

#pragma unroll
    for (int i = 0; i < 4; i++)
#pragma unroll
        for (int hh = 0; hh < 2; hh++) {
            float v = sume[i][hh];
            v += __shfl_xor_sync(0xffffffffu, v, 1);
            v += __shfl_xor_sync(0xffffffffu, v, 2);
            if ((lane & 3) == 0)
                atomicAdd(&colsum[wm * 64 + i * 16 + (lane >> 2) + hh * 8], v);
        }
    __syncthreads();
    if (tid < 128)
        g_linv[((size_t)b * NH + h) * SEQ + k0 + tid] = 1.0f / colsum[tid];
}

// ---------------------------------------------------------------------------
// Kernel 2: out[q,:] = sum_k exp(s[q,k]) * (linv[k]*v[k,:]).
// All-fp16 single-pass gemms with the (P-1) identity:
//   out = sum_k (P-1)*V'' + sum_k V''          (V'' = 1024*linv*V, fp16)
// T = sum_k V'' accumulated UNROUNDED in f32. Epilogue: out = (o + T)/1024.
// ---------------------------------------------------------------------------
__global__ void __launch_bounds__(256, 2) k2_attnv(const float* __restrict__ Qg,
                                                   const float* __restrict__ Kg,
                                                   const float* __restrict__ Vg) {
    extern __shared__ u32 smu[];
    u32* Qa = smu;              // fp16 A-pack 128q x 64d : 4096 u32
    u32* Kp = smu + 4096;       // fp16 B-pack 128k x 64d : 4224 u32
    u32* Vp = smu + 8320;       // fp16 B-pack 128k x 64d : 4224 u32  (FIXED size)
    float* Tsc = (float*)(smu + 12544);   // 256x4 partial T : 1024 u32
    float* Tf  = (float*)(smu + 13568);   // reduced T[64]
    // total 13632 u32 = 54528 B -> 2 CTAs/SM

    int tid = threadIdx.x, lane = tid & 31, w = tid >> 5;
    int b = blockIdx.z, h = blockIdx.y, q0 = blockIdx.x << 7;

    const float* Qb = Qg + ((size_t)b * SEQ + q0) * DIM + h * HD;
    const float* Kbase = Kg + (size_t)b * SEQ * DIM + h * HD;
    const float* Vbase = Vg + (size_t)b * SEQ * DIM + h * HD;
    const float* linv = g_linv + ((size_t)b * NH + h) * SEQ;

    int rb = tid >> 4, c4 = (tid & 15) << 2;
#pragma unroll
    for (int it = 0; it < 8; it++) {
        int r = rb + (it << 4);
        stA16f(Qa, r, c4, *(const float4*)(Qb + (size_t)r * DIM + c4));
    }

    float o[8][4];
#pragma unroll
    for (int nt = 0; nt < 8; nt++)
#pragma unroll
        for (int t = 0; t < 4; t++) o[nt][t] = 0.f;
    float Tl[4] = {0.f, 0.f, 0.f, 0.f};

    for (int k0 = 0; k0 < SEQ; k0 += 128) {
        __syncthreads();   // previous tile fully consumed
        // K tile -> fp16 B-pack
#pragma unroll
        for (int it = 0; it < 8; it++) {
            int n = rb + (it << 4);
            stB16f<16>(Kp, n, c4,
                       *(const float4*)(Kbase + (size_t)(k0 + n) * DIM + c4));
        }
        // V'' = 1024*linv*V -> fp16 B-pack; T accumulates unrounded V''
#pragma unroll
        for (int it = 0; it < 8; it++) {
            int kt = rb + (it << 4);
            float rl = __ldg(linv + k0 + kt) * 1024.0f;
            float4 v = *(const float4*)(Vbase + (size_t)(k0 + kt) * DIM + c4);
            v.x *= rl; v.y *= rl; v.z *= rl; v.w *= rl;
            Tl[0] += v.x; Tl[1] += v.y; Tl[2] += v.z; Tl[3] += v.w;
            float4 oth;
            oth.x = __shfl_xor_sync(0xffffffffu, v.x, 16);
            oth.y = __shfl_xor_sync(0xffffffffu, v.y, 16);
            oth.z = __shfl_xor_sync(0xffffffffu, v.z, 16);
            oth.w = __shfl_xor_sync(0xffffffffu, v.w, 16);
            float4 ve, vo;
            if (lane & 16) { ve = oth; vo = v; } else { ve = v; vo = oth; }
            // one writer per pair; alternate halves of warp for STS balance
            if (((lane >> 4) & 1) == (it & 1)) {
                int ke = kt & ~1;
                int ksv = ke >> 4, kk = ke & 15;
                int c = (kk & 7) >> 1, breg = kk >> 3;
                const float* pe = &ve.x; const float* po = &vo.x;
#pragma unroll
                for (int j = 0; j < 4; j++) {
                    int d = c4 + j;
                    int idx = ((ksv * 8 + (d >> 3)) * 33 + ((d & 7) << 2) + c) * 2 + breg;
                    Vp[idx] = f16x2_rn(po[j], pe[j]);
                }
            }
        }
        __syncthreads();

        // two 64-col k-halves: gemm1 half -> (exp-1) -> gemm2 half
#pragma unroll
        for (int half = 0; half < 2; half++) {
            float acc[8][4];
#pragma unroll
            for (int nt = 0; nt < 8; nt++)
#pragma unroll
                for (int tt = 0; tt < 4; tt++) acc[nt][tt] = 0.f;
#pragma unroll
            for (int ks = 0; ks < 4; ks++) {
                uint4 a = ldA16(Qa, ks, w, lane);
#pragma unroll
                for (int nt = 0; nt < 8; nt++) {
                    uint2 bf = ldB16<16>(Kp, ks, half * 8 + nt, lane);
                    mma16f(acc[nt], a, bf);
                }
            }

#pragma unroll
            for (int j2 = 0; j2 < 4; j2++) {
                float e0 = __expf(acc[2 * j2][0] * SCALE) - 1.0f;
                float e1 = __expf(acc[2 * j2][1] * SCALE) - 1.0f;
                float e2 = __expf(acc[2 * j2][2] * SCALE) - 1.0f;
                float e3 = __expf(acc[2 * j2][3] * SCALE) - 1.0f;
                float e4 = __expf(acc[2 * j2 + 1][0] * SCALE) - 1.0f;
                float e5 = __expf(acc[2 * j2 + 1][1] * SCALE) - 1.0f;
                float e6 = __expf(acc[2 * j2 + 1][2] * SCALE) - 1.0f;
                float e7 = __expf(acc[2 * j2 + 1][3] * SCALE) - 1.0f;
                uint4 ah;
                ah.x = f16x2_rn(e1, e0);
                ah.y = f16x2_rn(e3, e2);
                ah.z = f16x2_rn(e5, e4);
                ah.w = f16x2_rn(e7, e6);
                int ks2 = half * 4 + j2;
#pragma unroll
                for (int nt = 0; nt < 8; nt++) {
                    uint2 bv = ldB16<8>(Vp, ks2, nt, lane);
                    mma16f(o[nt], ah, bv);
                }
            }
        }
    }

    // reduce T across threads: Tsc[tid][j] -> Tf[d]
    __syncthreads();
#pragma unroll
    for (int j = 0; j < 4; j++) Tsc[tid * 4 + j] = Tl[j];
    __syncthreads();
    if (tid < 64) {
        float s = 0.f;
#pragma unroll
        for (int r2 = 0; r2 < 16; r2++)
            s += Tsc[(r2 * 16 + (tid >> 2)) * 4 + (tid & 3)];
        Tf[tid] = s;
    }
    __syncthreads();

    const float inv1024 = 1.0f / 1024.0f;
    int r = lane >> 2, c2 = (lane & 3) << 1;
    float* obase = g_att + ((size_t)b * SEQ + q0 + 16 * w + r) * DIM + h * HD;
#pragma unroll
    for (int nt = 0; nt < 8; nt++) {
        int d0 = nt * 8 + c2;
        float t0 = Tf[d0], t1 = Tf[d0 + 1];
        *(float2*)(obase + d0) =
            make_float2((o[nt][0] + t0) * inv1024, (o[nt][1] + t1) * inv1024);
        *(float2*)(obase + (size_t)8 * DIM + d0) =
            make_float2((o[nt][2] + t0) * inv1024, (o[nt][3] + t1) * inv1024);
    }
}

// ---------------------------------------------------------------------------
// Kernel 3: out = g_att @ W^T + b.  bf16 3-pass split. (unchanged)
// ---------------------------------------------------------------------------
__global__ void __launch_bounds__(256, 2) k3_linear(const float* __restrict__ Wg,
                                                    const float* __restrict__ bg,
                                                    float* __restrict__ Og) {
    extern __shared__ u32 smu[];
    u32* Xh = smu;             // 4096
    u32* Xl = smu + 4096;      // 4096
    u32* Wh = smu + 8192;      // 4224
    u32* Wl = smu + 12416;     // 4224

    int tid = threadIdx.x, lane = tid & 31, w = tid >> 5;
    int wm = w >> 2, wn = w & 3;
    int n0 = blockIdx.x << 7, m0 = blockIdx.y << 7;

    float acc[4][4][4];
#pragma unroll
    for (int i = 0; i < 4; i++)
#pragma unroll
        for (int j = 0; j < 4; j++)
#pragma unroll
            for (int t = 0; t < 4; t++) acc[i][j][t] = 0.f;

    int rb = tid >> 4, c4 = (tid & 15) << 2;
    for (int d0 = 0; d0 < DIM; d0 += 64) {
        __syncthreads();
#pragma unroll
        for (int it = 0; it < 8; it++) {
            int r = rb + (it << 4);
            float4 x = *(const float4*)(g_att + (size_t)(m0 + r) * DIM + d0 + c4);
            float4 wv = *(const float4*)(Wg + (size_t)(n0 + r) * DIM + d0 + c4);
            const float* xf = &x.x; const float* wf = &wv.x;
            int ks = c4 >> 4, kkb = c4 & 15;
#pragma unroll
            for (int p = 0; p < 2; p++) {
                int kk = kkb + 2 * p;
                int c = (kk & 7) >> 1;
                {
                    int slot = ((r >> 3) & 1) | ((kk >> 3) << 1);
                    int idx = ((ks * 8 + (r >> 4)) * 32 + ((r & 7) << 2) + c) * 4 + slot;
                    float a = xf[2 * p], bb = xf[2 * p + 1];
                    Xh[idx] = prmt_hi(__float_as_uint(a), __float_as_uint(bb));
                    Xl[idx] = bf16x2_rn(bb - truncb(bb), a - truncb(a));
                }
                {
                    int breg = kk >> 3;
                    int idx = ((ks * 16 + (r >> 3)) * 33 + ((r & 7) << 2) + c) * 2 + breg;
                    float a = wf[2 * p], bb = wf[2 * p + 1];
                    Wh[idx] = prmt_hi(__float_as_uint(a), __float_as_uint(bb));
                    Wl[idx] = bf16x2_rn(bb - truncb(bb), a - truncb(a));
                }
            }
        }
        __syncthreads();

#pragma unroll
        for (int ks = 0; ks < 4; ks++) {
            uint4 ah[4], al[4]; uint2 bh[4], bl[4];
#pragma unroll
            for (int i = 0; i < 4; i++) {
                ah[i] = ldA16(Xh, ks, wm * 4 + i, lane);
                al[i] = ldA16(Xl, ks, wm * 4 + i, lane);
            }
#pragma unroll
            for (int j = 0; j < 4; j++) {
                bh[j] = ldB16<16>(Wh, ks, wn * 4 + j, lane);
                bl[j] = ldB16<16>(Wl, ks, wn * 4 + j, lane);
            }
#pragma unroll
            for (int i = 0; i < 4; i++)
#pragma unroll
                for (int j = 0; j < 4; j++) {
                    mma16(acc[i][j], ah[i], bh[j]);
                    mma16(acc[i][j], ah[i], bl[j]);
                    mma16(acc[i][j], al[i], bh[j]);
                }
        }
    }

#pragma unroll
    for (int i = 0; i < 4; i++)
#pragma unroll
        for (int j = 0; j < 4; j++) {
            int r = wm * 64 + i * 16 + (lane >> 2);
            int n = wn * 32 + j * 8 + ((lane & 3) << 1);
            float2 bb = *(const float2*)(bg + n0 + n);
            float* p = Og + (size_t)(m0 + r) * DIM + n0 + n;
            *(float2*)p = make_float2(acc[i][j][0] + bb.x, acc[i][j][1] + bb.y);
            *(float2*)(p + (size_t)8 * DIM) =
                make_float2(acc[i][j][2] + bb.x, acc[i][j][3] + bb.y);
        }
}

// ---------------------------------------------------------------------------

extern "C" void kernel_launch(void* const* d_in, const int* in_sizes, int n_in,
                              void* d_out, int out_size) {
    const float* Q = (const float*)d_in[0];
    const float* K = (const float*)d_in[1];
    const float* V = (const float*)d_in[2];
    const float* W = (const float*)d_in[3];
    const float* bias = (const float*)d_in[4];
    float* out = (float*)d_out;
    (void)in_sizes; (void)n_in; (void)out_size;

    const int smem1 = (4096 + 4224 + 128) * 4;   // 33792
    const int smem2 = 13632 * 4;                 // 54528
    const int smem3 = 16640 * 4;                 // 66560

    cudaFuncSetAttribute(k1_colsum, cudaFuncAttributeMaxDynamicSharedMemorySize, smem1);
    cudaFuncSetAttribute(k2_attnv,  cudaFuncAttributeMaxDynamicSharedMemorySize, smem2);
    cudaFuncSetAttribute(k3_linear, cudaFuncAttributeMaxDynamicSharedMemorySize, smem3);

    dim3 gAttn(SEQ / 128, NH, NB);          // 1024 CTAs
    k1_colsum<<<gAttn, 256, smem1>>>(Q, K);
    k2_attnv<<<gAttn, 256, smem2>>>(Q, K, V);

    dim3 gLin(DIM / 128, (NB * SEQ) / 128); // 512 CTAs
    k3_linear<<<gLin, 256, smem3>>>(W, bias, out);
}

// round 12
// speedup vs baseline: 1.9900x; 1.1347x over previous
#include <cuda_runtime.h>

#define NB 4
#define NH 16
#define SEQ 2048
#define DIM 1024
#define HD 64
#define SCALE 0.03125f   // 1/sqrt(1024)

typedef unsigned int u32;

// Scratch (allocation-free rule: __device__ globals)
__device__ float g_linv[NB * NH * SEQ];
__device__ float g_att[(size_t)NB * SEQ * DIM];

// ---------------------------------------------------------------------------
// Low-level helpers (portable sm_80+ PTX)
// ---------------------------------------------------------------------------
__device__ __forceinline__ u32 bf16x2_rn(float hi, float lo) {
    u32 r; asm("cvt.rn.bf16x2.f32 %0, %1, %2;" : "=r"(r) : "f"(hi), "f"(lo)); return r;
}
__device__ __forceinline__ u32 f16x2_rn(float hi, float lo) {
    u32 r; asm("cvt.rn.f16x2.f32 %0, %1, %2;" : "=r"(r) : "f"(hi), "f"(lo)); return r;
}

// m16n8k16 bf16 mma
__device__ __forceinline__ void mma16(float c[4], uint4 a, uint2 b) {
    asm volatile(
        "mma.sync.aligned.m16n8k16.row.col.f32.bf16.bf16.f32 "
        "{%0,%1,%2,%3}, {%4,%5,%6,%7}, {%8,%9}, {%0,%1,%2,%3};"
        : "+f"(c[0]), "+f"(c[1]), "+f"(c[2]), "+f"(c[3])
        : "r"(a.x), "r"(a.y), "r"(a.z), "r"(a.w), "r"(b.x), "r"(b.y));
}
// m16n8k16 fp16 mma
__device__ __forceinline__ void mma16f(float c[4], uint4 a, uint2 b) {
    asm volatile(
        "mma.sync.aligned.m16n8k16.row.col.f32.f16.f16.f32 "
        "{%0,%1,%2,%3}, {%4,%5,%6,%7}, {%8,%9}, {%0,%1,%2,%3};"
        : "+f"(c[0]), "+f"(c[1]), "+f"(c[2]), "+f"(c[3])
        : "r"(a.x), "r"(a.y), "r"(a.z), "r"(a.w), "r"(b.x), "r"(b.y));
}

// ---------------------------------------------------------------------------
// 16-bit fragment packs (m16n8k16). A-pack: [ks][mt(8)][lane] uint4.
// B-pack padded: [ks][nt][33 lane-pairs] uint2.
// ---------------------------------------------------------------------------
__device__ __forceinline__ uint4 ldA16(const u32* A, int ks, int mt, int lane) {
    return *(const uint4*)(A + ((size_t)((ks * 8 + mt) * 32 + lane)) * 4);
}
template<int NT>
__device__ __forceinline__ uint2 ldB16(const u32* B, int ks, int nt, int lane) {
    return *(const uint2*)(B + ((size_t)((ks * NT + nt) * 33 + lane)) * 2);
}
// bf16 stores (k1)
__device__ __forceinline__ void stA16_rn(u32* A, int r, int c4, float4 v) {
    int ks = c4 >> 4, kkb = c4 & 15;
    const float* f = &v.x;
#pragma unroll
    for (int p = 0; p < 2; p++) {
        int kk = kkb + 2 * p;
        int c = (kk & 7) >> 1, slot = ((r >> 3) & 1) | ((kk >> 3) << 1);
        int idx = ((ks * 8 + (r >> 4)) * 32 + ((r & 7) << 2) + c) * 4 + slot;
        A[idx] = bf16x2_rn(f[2 * p + 1], f[2 * p]);
    }
}
template<int NT>
__device__ __forceinline__ void stB16_rn(u32* B, int n, int c4, float4 v) {
    int ks = c4 >> 4, kkb = c4 & 15;
    const float* f = &v.x;
#pragma unroll
    for (int p = 0; p < 2; p++) {
        int kk = kkb + 2 * p;
        int c = (kk & 7) >> 1, breg = kk >> 3;
        int idx = ((ks * NT + (n >> 3)) * 33 + ((n & 7) << 2) + c) * 2 + breg;
        B[idx] = bf16x2_rn(f[2 * p + 1], f[2 * p]);
    }
}
// fp16 stores (k2/k3)
__device__ __forceinline__ void stA16f(u32* A, int r, int c4, float4 v) {
    int ks = c4 >> 4, kkb = c4 & 15;
    const float* f = &v.x;
#pragma unroll
    for (int p = 0; p < 2; p++) {
        int kk = kkb + 2 * p;
        int c = (kk & 7) >> 1, slot = ((r >> 3) & 1) | ((kk >> 3) << 1);
        int idx = ((ks * 8 + (r >> 4)) * 32 + ((r & 7) << 2) + c) * 4 + slot;
        A[idx] = f16x2_rn(f[2 * p + 1], f[2 * p]);
    }
}
template<int NT>
__device__ __forceinline__ void stB16f(u32* B, int n, int c4, float4 v) {
    int ks = c4 >> 4, kkb = c4 & 15;
    const float* f = &v.x;
#pragma unroll
    for (int p = 0; p < 2; p++) {
        int kk = kkb + 2 * p;
        int c = (kk & 7) >> 1, breg = kk >> 3;
        int idx = ((ks * NT + (n >> 3)) * 33 + ((n & 7) << 2) + c) * 2 + breg;
        B[idx] = f16x2_rn(f[2 * p + 1], f[2 * p]);
    }
}

// ---------------------------------------------------------------------------
// Kernel 1: l[k] = sum_q exp(s[q,k]); store 1/l.
// q-group loop split in halves (acc 32 regs) + launch_bounds(256,3) for
// 3 CTAs/SM latency hiding. Math order per element unchanged.
// ---------------------------------------------------------------------------
__global__ void __launch_bounds__(256, 3) k1_colsum(const float* __restrict__ Qg,
                                                    const float* __restrict__ Kg) {
    extern __shared__ u32 smu[];
    u32* Ka = smu;                       // 4096 u32
    u32* Qb = smu + 4096;                // 4224 u32
    float* colsum = (float*)(smu + 8320);
    int tid = threadIdx.x, lane = tid & 31, w = tid >> 5;
    int wm = w >> 2, wn = w & 3;
    int b = blockIdx.z, h = blockIdx.y, k0 = blockIdx.x << 7;

    const float* Kb = Kg + ((size_t)b * SEQ + k0) * DIM + h * HD;
    const float* Qbase = Qg + (size_t)b * SEQ * DIM + h * HD;

    int rb = tid >> 4, c4 = (tid & 15) << 2;
#pragma unroll
    for (int it = 0; it < 8; it++) {
        int r = rb + (it << 4);
        stA16_rn(Ka, r, c4, *(const float4*)(Kb + (size_t)r * DIM + c4));
    }
    if (tid < 128) colsum[tid] = 0.f;

    float sume[4][2];
#pragma unroll
    for (int i = 0; i < 4; i++) { sume[i][0] = 0.f; sume[i][1] = 0.f; }

    for (int q0 = 0; q0 < SEQ; q0 += 128) {
        __syncthreads();
#pragma unroll
        for (int it = 0; it < 8; it++) {
            int n = rb + (it << 4);
            stB16_rn<16>(Qb, n, c4,
                         *(const float4*)(Qbase + (size_t)(q0 + n) * DIM + c4));
        }
        __syncthreads();

#pragma unroll
        for (int jh = 0; jh < 2; jh++) {
            float acc[4][2][4];
#pragma unroll
            for (int i = 0; i < 4; i++)
#pragma unroll
                for (int j = 0; j < 2; j++)
#pragma unroll
                    for (int t = 0; t < 4; t++) acc[i][j][t] = 0.f;

#pragma unroll
            for (int ks = 0; ks < 4; ks++) {
                uint4 af[4]; uint2 bf[2];
#pragma unroll
                for (int i = 0; i < 4; i++) af[i] = ldA16(Ka, ks, wm * 4 + i, lane);
#pragma unroll
                for (int j = 0; j < 2; j++)
                    bf[j] = ldB16<16>(Qb, ks, wn * 4 + jh * 2 + j, lane);
#pragma unroll
                for (int i = 0; i < 4; i++)
#pragma unroll
                    for (int j = 0; j < 2; j++) mma16(acc[i][j], af[i], bf[j]);
            }
#pragma unroll
            for (int i = 0; i < 4; i++)
#pragma unroll
                for (int j = 0; j < 2; j++) {
                    sume[i][0] += __expf(acc[i][j][0] * SCALE) + __expf(acc[i][j][1] * SCALE);
                    sume[i][1] += __expf(acc[i][j][2] * SCALE) + __expf(acc[i][j][3] * SCALE);
                }
        }
    }

#pragma unroll
    for (int i = 0; i < 4; i++)
#pragma unroll
        for (int hh = 0; hh < 2; hh++) {
            float v = sume[i][hh];
            v += __shfl_xor_sync(0xffffffffu, v, 1);
            v += __shfl_xor_sync(0xffffffffu, v, 2);
            if ((lane & 3) == 0)
                atomicAdd(&colsum[wm * 64 + i * 16 + (lane >> 2) + hh * 8], v);
        }
    __syncthreads();
    if (tid < 128)
        g_linv[((size_t)b * NH + h) * SEQ + k0 + tid] = 1.0f / colsum[tid];
}

// ---------------------------------------------------------------------------
// Kernel 2: out[q,:] = sum_k exp(s[q,k]) * (linv[k]*v[k,:]).  (r11, proven)
// All-fp16 single-pass gemms with the (P-1) identity:
//   out = sum_k (P-1)*V'' + sum_k V''          (V'' = 1024*linv*V, fp16)
// ---------------------------------------------------------------------------
__global__ void __launch_bounds__(256, 2) k2_attnv(const float* __restrict__ Qg,
                                                   const float* __restrict__ Kg,
                                                   const float* __restrict__ Vg) {
    extern __shared__ u32 smu[];
    u32* Qa = smu;              // fp16 A-pack 128q x 64d : 4096 u32
    u32* Kp = smu + 4096;       // fp16 B-pack 128k x 64d : 4224 u32
    u32* Vp = smu + 8320;       // fp16 B-pack 128k x 64d : 4224 u32
    float* Tsc = (float*)(smu + 12544);   // 256x4 partial T : 1024 u32
    float* Tf  = (float*)(smu + 13568);   // reduced T[64]
    // total 13632 u32 = 54528 B -> 2 CTAs/SM

    int tid = threadIdx.x, lane = tid & 31, w = tid >> 5;
    int b = blockIdx.z, h = blockIdx.y, q0 = blockIdx.x << 7;

    const float* Qb = Qg + ((size_t)b * SEQ + q0) * DIM + h * HD;
    const float* Kbase = Kg + (size_t)b * SEQ * DIM + h * HD;
    const float* Vbase = Vg + (size_t)b * SEQ * DIM + h * HD;
    const float* linv = g_linv + ((size_t)b * NH + h) * SEQ;

    int rb = tid >> 4, c4 = (tid & 15) << 2;
#pragma unroll
    for (int it = 0; it < 8; it++) {
        int r = rb + (it << 4);
        stA16f(Qa, r, c4, *(const float4*)(Qb + (size_t)r * DIM + c4));
    }

    float o[8][4];
#pragma unroll
    for (int nt = 0; nt < 8; nt++)
#pragma unroll
        for (int t = 0; t < 4; t++) o[nt][t] = 0.f;
    float Tl[4] = {0.f, 0.f, 0.f, 0.f};

    for (int k0 = 0; k0 < SEQ; k0 += 128) {
        __syncthreads();
#pragma unroll
        for (int it = 0; it < 8; it++) {
            int n = rb + (it << 4);
            stB16f<16>(Kp, n, c4,
                       *(const float4*)(Kbase + (size_t)(k0 + n) * DIM + c4));
        }
#pragma unroll
        for (int it = 0; it < 8; it++) {
            int kt = rb + (it << 4);
            float rl = __ldg(linv + k0 + kt) * 1024.0f;
            float4 v = *(const float4*)(Vbase + (size_t)(k0 + kt) * DIM + c4);
            v.x *= rl; v.y *= rl; v.z *= rl; v.w *= rl;
            Tl[0] += v.x; Tl[1] += v.y; Tl[2] += v.z; Tl[3] += v.w;
            float4 oth;
            oth.x = __shfl_xor_sync(0xffffffffu, v.x, 16);
            oth.y = __shfl_xor_sync(0xffffffffu, v.y, 16);
            oth.z = __shfl_xor_sync(0xffffffffu, v.z, 16);
            oth.w = __shfl_xor_sync(0xffffffffu, v.w, 16);
            float4 ve, vo;
            if (lane & 16) { ve = oth; vo = v; } else { ve = v; vo = oth; }
            if (((lane >> 4) & 1) == (it & 1)) {
                int ke = kt & ~1;
                int ksv = ke >> 4, kk = ke & 15;
                int c = (kk & 7) >> 1, breg = kk >> 3;
                const float* pe = &ve.x; const float* po = &vo.x;
#pragma unroll
                for (int j = 0; j < 4; j++) {
                    int d = c4 + j;
                    int idx = ((ksv * 8 + (d >> 3)) * 33 + ((d & 7) << 2) + c) * 2 + breg;
                    Vp[idx] = f16x2_rn(po[j], pe[j]);
                }
            }
        }
        __syncthreads();

#pragma unroll
        for (int half = 0; half < 2; half++) {
            float acc[8][4];
#pragma unroll
            for (int nt = 0; nt < 8; nt++)
#pragma unroll
                for (int tt = 0; tt < 4; tt++) acc[nt][tt] = 0.f;
#pragma unroll
            for (int ks = 0; ks < 4; ks++) {
                uint4 a = ldA16(Qa, ks, w, lane);
#pragma unroll
                for (int nt = 0; nt < 8; nt++) {
                    uint2 bf = ldB16<16>(Kp, ks, half * 8 + nt, lane);
                    mma16f(acc[nt], a, bf);
                }
            }

#pragma unroll
            for (int j2 = 0; j2 < 4; j2++) {
                float e0 = __expf(acc[2 * j2][0] * SCALE) - 1.0f;
                float e1 = __expf(acc[2 * j2][1] * SCALE) - 1.0f;
                float e2 = __expf(acc[2 * j2][2] * SCALE) - 1.0f;
                float e3 = __expf(acc[2 * j2][3] * SCALE) - 1.0f;
                float e4 = __expf(acc[2 * j2 + 1][0] * SCALE) - 1.0f;
                float e5 = __expf(acc[2 * j2 + 1][1] * SCALE) - 1.0f;
                float e6 = __expf(acc[2 * j2 + 1][2] * SCALE) - 1.0f;
                float e7 = __expf(acc[2 * j2 + 1][3] * SCALE) - 1.0f;
                uint4 ah;
                ah.x = f16x2_rn(e1, e0);
                ah.y = f16x2_rn(e3, e2);
                ah.z = f16x2_rn(e5, e4);
                ah.w = f16x2_rn(e7, e6);
                int ks2 = half * 4 + j2;
#pragma unroll
                for (int nt = 0; nt < 8; nt++) {
                    uint2 bv = ldB16<8>(Vp, ks2, nt, lane);
                    mma16f(o[nt], ah, bv);
                }
            }
        }
    }

    __syncthreads();
#pragma unroll
    for (int j = 0; j < 4; j++) Tsc[tid * 4 + j] = Tl[j];
    __syncthreads();
    if (tid < 64) {
        float s = 0.f;
#pragma unroll
        for (int r2 = 0; r2 < 16; r2++)
            s += Tsc[(r2 * 16 + (tid >> 2)) * 4 + (tid & 3)];
        Tf[tid] = s;
    }
    __syncthreads();

    const float inv1024 = 1.0f / 1024.0f;
    int r = lane >> 2, c2 = (lane & 3) << 1;
    float* obase = g_att + ((size_t)b * SEQ + q0 + 16 * w + r) * DIM + h * HD;
#pragma unroll
    for (int nt = 0; nt < 8; nt++) {
        int d0 = nt * 8 + c2;
        float t0 = Tf[d0], t1 = Tf[d0 + 1];
        *(float2*)(obase + d0) =
            make_float2((o[nt][0] + t0) * inv1024, (o[nt][1] + t1) * inv1024);
        *(float2*)(obase + (size_t)8 * DIM + d0) =
            make_float2((o[nt][2] + t0) * inv1024, (o[nt][3] + t1) * inv1024);
    }
}

// ---------------------------------------------------------------------------
// Kernel 3: out = g_att @ W^T + b.  SINGLE-PASS fp16 (was 3-pass bf16).
// Error ~3.4e-4 (fp16-rn on X ~O(1), W ~0.03; sqrt(1024) averaging).
// ---------------------------------------------------------------------------
__global__ void __launch_bounds__(256, 2) k3_linear(const float* __restrict__ Wg,
                                                    const float* __restrict__ bg,
                                                    float* __restrict__ Og) {
    extern __shared__ u32 smu[];
    u32* Xp = smu;             // fp16 A-pack : 4096 u32
    u32* Wp = smu + 4096;      // fp16 B-pack : 4224 u32
    // total 8320 u32 = 33280 B

    int tid = threadIdx.x, lane = tid & 31, w = tid >> 5;
    int wm = w >> 2, wn = w & 3;
    int n0 = blockIdx.x << 7, m0 = blockIdx.y << 7;

    float acc[4][4][4];
#pragma unroll
    for (int i = 0; i < 4; i++)
#pragma unroll
        for (int j = 0; j < 4; j++)
#pragma unroll
            for (int t = 0; t < 4; t++) acc[i][j][t] = 0.f;

    int rb = tid >> 4, c4 = (tid & 15) << 2;
    for (int d0 = 0; d0 < DIM; d0 += 64) {
        __syncthreads();
#pragma unroll
        for (int it = 0; it < 8; it++) {
            int r = rb + (it << 4);
            stA16f(Xp, r, c4,
                   *(const float4*)(g_att + (size_t)(m0 + r) * DIM + d0 + c4));
            stB16f<16>(Wp, r, c4,
                       *(const float4*)(Wg + (size_t)(n0 + r) * DIM + d0 + c4));
        }
        __syncthreads();

#pragma unroll
        for (int ks = 0; ks < 4; ks++) {
            uint4 ah[4]; uint2 bh[4];
#pragma unroll
            for (int i = 0; i < 4; i++) ah[i] = ldA16(Xp, ks, wm * 4 + i, lane);
#pragma unroll
            for (int j = 0; j < 4; j++) bh[j] = ldB16<16>(Wp, ks, wn * 4 + j, lane);
#pragma unroll
            for (int i = 0; i < 4; i++)
#pragma unroll
                for (int j = 0; j < 4; j++)
                    mma16f(acc[i][j], ah[i], bh[j]);
        }
    }

#pragma unroll
    for (int i = 0; i < 4; i++)
#pragma unroll
        for (int j = 0; j < 4; j++) {
            int r = wm * 64 + i * 16 + (lane >> 2);
            int n = wn * 32 + j * 8 + ((lane & 3) << 1);
            float2 bb = *(const float2*)(bg + n0 + n);
            float* p = Og + (size_t)(m0 + r) * DIM + n0 + n;
            *(float2*)p = make_float2(acc[i][j][0] + bb.x, acc[i][j][1] + bb.y);
            *(float2*)(p + (size_t)8 * DIM) =
                make_float2(acc[i][j][2] + bb.x, acc[i][j][3] + bb.y);
        }
}

// ---------------------------------------------------------------------------

extern "C" void kernel_launch(void* const* d_in, const int* in_sizes, int n_in,
                              void* d_out, int out_size) {
    const float* Q = (const float*)d_in[0];
    const float* K = (const float*)d_in[1];
    const float* V = (const float*)d_in[2];
    const float* W = (const float*)d_in[3];
    const float* bias = (const float*)d_in[4];
    float* out = (float*)d_out;
    (void)in_sizes; (void)n_in; (void)out_size;

    const int smem1 = (4096 + 4224 + 128) * 4;   // 33792
    const int smem2 = 13632 * 4;                 // 54528
    const int smem3 = 8320 * 4;                  // 33280

    cudaFuncSetAttribute(k1_colsum, cudaFuncAttributeMaxDynamicSharedMemorySize, smem1);
    cudaFuncSetAttribute(k2_attnv,  cudaFuncAttributeMaxDynamicSharedMemorySize, smem2);
    cudaFuncSetAttribute(k3_linear, cudaFuncAttributeMaxDynamicSharedMemorySize, smem3);

    dim3 gAttn(SEQ / 128, NH, NB);          // 1024 CTAs
    k1_colsum<<<gAttn, 256, smem1>>>(Q, K);
    k2_attnv<<<gAttn, 256, smem2>>>(Q, K, V);

    dim3 gLin(DIM / 128, (NB * SEQ) / 128); // 512 CTAs
    k3_linear<<<gLin, 256, smem3>>>(W, bias, out);
}

// round 13
// speedup vs baseline: 2.1346x; 1.0726x over previous
#include <cuda_runtime.h>

#define NB 4
#define NH 16
#define SEQ 2048
#define DIM 1024
#define HD 64
#define SCALE 0.03125f   // 1/sqrt(1024)

typedef unsigned int u32;

// Scratch (allocation-free rule: __device__ globals)
__device__ float g_linv[NB * NH * SEQ];
__device__ float g_att[(size_t)NB * SEQ * DIM];

// ---------------------------------------------------------------------------
// Low-level helpers (portable sm_80+ PTX)
// ---------------------------------------------------------------------------
__device__ __forceinline__ u32 bf16x2_rn(float hi, float lo) {
    u32 r; asm("cvt.rn.bf16x2.f32 %0, %1, %2;" : "=r"(r) : "f"(hi), "f"(lo)); return r;
}
__device__ __forceinline__ u32 f16x2_rn(float hi, float lo) {
    u32 r; asm("cvt.rn.f16x2.f32 %0, %1, %2;" : "=r"(r) : "f"(hi), "f"(lo)); return r;
}
__device__ __forceinline__ u32 ex2h2(u32 x) {     // 2 exps per MUFU op
    u32 r; asm("ex2.approx.f16x2 %0, %1;" : "=r"(r) : "r"(x)); return r;
}
__device__ __forceinline__ float2 h2f2(u32 e) {
    float2 f;
    asm("{.reg .b16 h0,h1; mov.b32 {h0,h1}, %2; cvt.f32.f16 %0, h0; cvt.f32.f16 %1, h1;}"
        : "=f"(f.x), "=f"(f.y) : "r"(e));
    return f;
}

// m16n8k16 bf16 mma
__device__ __forceinline__ void mma16(float c[4], uint4 a, uint2 b) {
    asm volatile(
        "mma.sync.aligned.m16n8k16.row.col.f32.bf16.bf16.f32 "
        "{%0,%1,%2,%3}, {%4,%5,%6,%7}, {%8,%9}, {%0,%1,%2,%3};"
        : "+f"(c[0]), "+f"(c[1]), "+f"(c[2]), "+f"(c[3])
        : "r"(a.x), "r"(a.y), "r"(a.z), "r"(a.w), "r"(b.x), "r"(b.y));
}
// m16n8k16 fp16 mma
__device__ __forceinline__ void mma16f(float c[4], uint4 a, uint2 b) {
    asm volatile(
        "mma.sync.aligned.m16n8k16.row.col.f32.f16.f16.f32 "
        "{%0,%1,%2,%3}, {%4,%5,%6,%7}, {%8,%9}, {%0,%1,%2,%3};"
        : "+f"(c[0]), "+f"(c[1]), "+f"(c[2]), "+f"(c[3])
        : "r"(a.x), "r"(a.y), "r"(a.z), "r"(a.w), "r"(b.x), "r"(b.y));
}

// ---------------------------------------------------------------------------
// 16-bit fragment packs (m16n8k16). A-pack: [ks][mt(8)][lane] uint4.
// B-pack padded: [ks][nt][33 lane-pairs] uint2.
// ---------------------------------------------------------------------------
__device__ __forceinline__ uint4 ldA16(const u32* A, int ks, int mt, int lane) {
    return *(const uint4*)(A + ((size_t)((ks * 8 + mt) * 32 + lane)) * 4);
}
template<int NT>
__device__ __forceinline__ uint2 ldB16(const u32* B, int ks, int nt, int lane) {
    return *(const uint2*)(B + ((size_t)((ks * NT + nt) * 33 + lane)) * 2);
}
// bf16 stores (k1)
__device__ __forceinline__ void stA16_rn(u32* A, int r, int c4, float4 v) {
    int ks = c4 >> 4, kkb = c4 & 15;
    const float* f = &v.x;
#pragma unroll
    for (int p = 0; p < 2; p++) {
        int kk = kkb + 2 * p;
        int c = (kk & 7) >> 1, slot = ((r >> 3) & 1) | ((kk >> 3) << 1);
        int idx = ((ks * 8 + (r >> 4)) * 32 + ((r & 7) << 2) + c) * 4 + slot;
        A[idx] = bf16x2_rn(f[2 * p + 1], f[2 * p]);
    }
}
template<int NT>
__device__ __forceinline__ void stB16_rn(u32* B, int n, int c4, float4 v) {
    int ks = c4 >> 4, kkb = c4 & 15;
    const float* f = &v.x;
#pragma unroll
    for (int p = 0; p < 2; p++) {
        int kk = kkb + 2 * p;
        int c = (kk & 7) >> 1, breg = kk >> 3;
        int idx = ((ks * NT + (n >> 3)) * 33 + ((n & 7) << 2) + c) * 2 + breg;
        B[idx] = bf16x2_rn(f[2 * p + 1], f[2 * p]);
    }
}
// fp16 stores (k2/k3)
__device__ __forceinline__ void stA16f(u32* A, int r, int c4, float4 v) {
    int ks = c4 >> 4, kkb = c4 & 15;
    const float* f = &v.x;
#pragma unroll
    for (int p = 0; p < 2; p++) {
        int kk = kkb + 2 * p;
        int c = (kk & 7) >> 1, slot = ((r >> 3) & 1) | ((kk >> 3) << 1);
        int idx = ((ks * 8 + (r >> 4)) * 32 + ((r & 7) << 2) + c) * 4 + slot;
        A[idx] = f16x2_rn(f[2 * p + 1], f[2 * p]);
    }
}
template<int NT>
__device__ __forceinline__ void stB16f(u32* B, int n, int c4, float4 v) {
    int ks = c4 >> 4, kkb = c4 & 15;
    const float* f = &v.x;
#pragma unroll
    for (int p = 0; p < 2; p++) {
        int kk = kkb + 2 * p;
        int c = (kk & 7) >> 1, breg = kk >> 3;
        int idx = ((ks * NT + (n >> 3)) * 33 + ((n & 7) << 2) + c) * 2 + breg;
        B[idx] = f16x2_rn(f[2 * p + 1], f[2 * p]);
    }
}

// ---------------------------------------------------------------------------
// Kernel 1: l[k] = sum_q exp(s[q,k]); store 1/l.
// r11 structure (acc[4][4][4], natural occupancy) + packed fp16 ex2:
// half the MUFU ops. Approx errors average out over the 2048-term sum.
// ---------------------------------------------------------------------------
__global__ void __launch_bounds__(256) k1_colsum(const float* __restrict__ Qg,
                                                 const float* __restrict__ Kg) {
    extern __shared__ u32 smu[];
    u32* Ka = smu;                       // 4096 u32
    u32* Qb = smu + 4096;                // 4224 u32
    float* colsum = (float*)(smu + 8320);
    int tid = threadIdx.x, lane = tid & 31, w = tid >> 5;
    int wm = w >> 2, wn = w & 3;
    int b = blockIdx.z, h = blockIdx.y, k0 = blockIdx.x << 7;

    const float* Kb = Kg + ((size_t)b * SEQ + k0) * DIM + h * HD;
    const float* Qbase = Qg + (size_t)b * SEQ * DIM + h * HD;

    const float C2 = SCALE * 1.4426950408889634f;   // SCALE * log2(e)

    int rb = tid >> 4, c4 = (tid & 15) << 2;
#pragma unroll
    for (int it = 0; it < 8; it++) {
        int r = rb + (it << 4);
        stA16_rn(Ka, r, c4, *(const float4*)(Kb + (size_t)r * DIM + c4));
    }
    if (tid < 128) colsum[tid] = 0.f;

    float sume[4][2];
#pragma unroll
    for (int i = 0; i < 4; i++) { sume[i][0] = 0.f; sume[i][1] = 0.f; }

    for (int q0 = 0; q0 < SEQ; q0 += 128) {
        __syncthreads();
#pragma unroll
        for (int it = 0; it < 8; it++) {
            int n = rb + (it << 4);
            stB16_rn<16>(Qb, n, c4,
                         *(const float4*)(Qbase + (size_t)(q0 + n) * DIM + c4));
        }
        __syncthreads();

        float acc[4][4][4];
#pragma unroll
        for (int i = 0; i < 4; i++)
#pragma unroll
            for (int j = 0; j < 4; j++)
#pragma unroll
                for (int t = 0; t < 4; t++) acc[i][j][t] = 0.f;

#pragma unroll
        for (int ks = 0; ks < 4; ks++) {
            uint4 af[4]; uint2 bf[4];
#pragma unroll
            for (int i = 0; i < 4; i++) af[i] = ldA16(Ka, ks, wm * 4 + i, lane);
#pragma unroll
            for (int j = 0; j < 4; j++) bf[j] = ldB16<16>(Qb, ks, wn * 4 + j, lane);
#pragma unroll
            for (int i = 0; i < 4; i++)
#pragma unroll
                for (int j = 0; j < 4; j++) mma16(acc[i][j], af[i], bf[j]);
        }
#pragma unroll
        for (int i = 0; i < 4; i++)
#pragma unroll
            for (int j = 0; j < 4; j++) {
                u32 e01 = ex2h2(f16x2_rn(acc[i][j][1] * C2, acc[i][j][0] * C2));
                u32 e23 = ex2h2(f16x2_rn(acc[i][j][3] * C2, acc[i][j][2] * C2));
                float2 f01 = h2f2(e01);
                float2 f23 = h2f2(e23);
                sume[i][0] += f01.x + f01.y;
                sume[i][1] += f23.x + f23.y;
            }
    }

#pragma unroll
    for (int i = 0; i < 4; i++)
#pragma unroll
        for (int hh = 0; hh < 2; hh++) {
            float v = sume[i][hh];
            v += __shfl_xor_sync(0xffffffffu, v, 1);
            v += __shfl_xor_sync(0xffffffffu, v, 2);
            if ((lane & 3) == 0)
                atomicAdd(&colsum[wm * 64 + i * 16 + (lane >> 2) + hh * 8], v);
        }
    __syncthreads();
    if (tid < 128)
        g_linv[((size_t)b * NH + h) * SEQ + k0 + tid] = 1.0f / colsum[tid];
}

// ---------------------------------------------------------------------------
// Kernel 2: out[q,:] = sum_k exp(s[q,k]) * (linv[k]*v[k,:]).  (r11, proven)
// ---------------------------------------------------------------------------
__global__ void __launch_bounds__(256, 2) k2_attnv(const float* __restrict__ Qg,
                                                   const float* __restrict__ Kg,
                                                   const float* __restrict__ Vg) {
    extern __shared__ u32 smu[];
    u32* Qa = smu;              // fp16 A-pack 128q x 64d : 4096 u32
    u32* Kp = smu + 4096;       // fp16 B-pack 128k x 64d : 4224 u32
    u32* Vp = smu + 8320;       // fp16 B-pack 128k x 64d : 4224 u32
    float* Tsc = (float*)(smu + 12544);   // 256x4 partial T : 1024 u32
    float* Tf  = (float*)(smu + 13568);   // reduced T[64]
    // total 13632 u32 = 54528 B -> 2 CTAs/SM

    int tid = threadIdx.x, lane = tid & 31, w = tid >> 5;
    int b = blockIdx.z, h = blockIdx.y, q0 = blockIdx.x << 7;

    const float* Qb = Qg + ((size_t)b * SEQ + q0) * DIM + h * HD;
    const float* Kbase = Kg + (size_t)b * SEQ * DIM + h * HD;
    const float* Vbase = Vg + (size_t)b * SEQ * DIM + h * HD;
    const float* linv = g_linv + ((size_t)b * NH + h) * SEQ;

    int rb = tid >> 4, c4 = (tid & 15) << 2;
#pragma unroll
    for (int it = 0; it < 8; it++) {
        int r = rb + (it << 4);
        stA16f(Qa, r, c4, *(const float4*)(Qb + (size_t)r * DIM + c4));
    }

    float o[8][4];
#pragma unroll
    for (int nt = 0; nt < 8; nt++)
#pragma unroll
        for (int t = 0; t < 4; t++) o[nt][t] = 0.f;
    float Tl[4] = {0.f, 0.f, 0.f, 0.f};

    for (int k0 = 0; k0 < SEQ; k0 += 128) {
        __syncthreads();
#pragma unroll
        for (int it = 0; it < 8; it++) {
            int n = rb + (it << 4);
            stB16f<16>(Kp, n, c4,
                       *(const float4*)(Kbase + (size_t)(k0 + n) * DIM + c4));
        }
#pragma unroll
        for (int it = 0; it < 8; it++) {
            int kt = rb + (it << 4);
            float rl = __ldg(linv + k0 + kt) * 1024.0f;
            float4 v = *(const float4*)(Vbase + (size_t)(k0 + kt) * DIM + c4);
            v.x *= rl; v.y *= rl; v.z *= rl; v.w *= rl;
            Tl[0] += v.x; Tl[1] += v.y; Tl[2] += v.z; Tl[3] += v.w;
            float4 oth;
            oth.x = __shfl_xor_sync(0xffffffffu, v.x, 16);
            oth.y = __shfl_xor_sync(0xffffffffu, v.y, 16);
            oth.z = __shfl_xor_sync(0xffffffffu, v.z, 16);
            oth.w = __shfl_xor_sync(0xffffffffu, v.w, 16);
            float4 ve, vo;
            if (lane & 16) { ve = oth; vo = v; } else { ve = v; vo = oth; }
            if (((lane >> 4) & 1) == (it & 1)) {
                int ke = kt & ~1;
                int ksv = ke >> 4, kk = ke & 15;
                int c = (kk & 7) >> 1, breg = kk >> 3;
                const float* pe = &ve.x; const float* po = &vo.x;
#pragma unroll
                for (int j = 0; j < 4; j++) {
                    int d = c4 + j;
                    int idx = ((ksv * 8 + (d >> 3)) * 33 + ((d & 7) << 2) + c) * 2 + breg;
                    Vp[idx] = f16x2_rn(po[j], pe[j]);
                }
            }
        }
        __syncthreads();

#pragma unroll
        for (int half = 0; half < 2; half++) {
            float acc[8][4];
#pragma unroll
            for (int nt = 0; nt < 8; nt++)
#pragma unroll
                for (int tt = 0; tt < 4; tt++) acc[nt][tt] = 0.f;
#pragma unroll
            for (int ks = 0; ks < 4; ks++) {
                uint4 a = ldA16(Qa, ks, w, lane);
#pragma unroll
                for (int nt = 0; nt < 8; nt++) {
                    uint2 bf = ldB16<16>(Kp, ks, half * 8 + nt, lane);
                    mma16f(acc[nt], a, bf);
                }
            }

#pragma unroll
            for (int j2 = 0; j2 < 4; j2++) {
                float e0 = __expf(acc[2 * j2][0] * SCALE) - 1.0f;
                float e1 = __expf(acc[2 * j2][1] * SCALE) - 1.0f;
                float e2 = __expf(acc[2 * j2][2] * SCALE) - 1.0f;
                float e3 = __expf(acc[2 * j2][3] * SCALE) - 1.0f;
                float e4 = __expf(acc[2 * j2 + 1][0] * SCALE) - 1.0f;
                float e5 = __expf(acc[2 * j2 + 1][1] * SCALE) - 1.0f;
                float e6 = __expf(acc[2 * j2 + 1][2] * SCALE) - 1.0f;
                float e7 = __expf(acc[2 * j2 + 1][3] * SCALE) - 1.0f;
                uint4 ah;
                ah.x = f16x2_rn(e1, e0);
                ah.y = f16x2_rn(e3, e2);
                ah.z = f16x2_rn(e5, e4);
                ah.w = f16x2_rn(e7, e6);
                int ks2 = half * 4 + j2;
#pragma unroll
                for (int nt = 0; nt < 8; nt++) {
                    uint2 bv = ldB16<8>(Vp, ks2, nt, lane);
                    mma16f(o[nt], ah, bv);
                }
            }
        }
    }

    __syncthreads();
#pragma unroll
    for (int j = 0; j < 4; j++) Tsc[tid * 4 + j] = Tl[j];
    __syncthreads();
    if (tid < 64) {
        float s = 0.f;
#pragma unroll
        for (int r2 = 0; r2 < 16; r2++)
            s += Tsc[(r2 * 16 + (tid >> 2)) * 4 + (tid & 3)];
        Tf[tid] = s;
    }
    __syncthreads();

    const float inv1024 = 1.0f / 1024.0f;
    int r = lane >> 2, c2 = (lane & 3) << 1;
    float* obase = g_att + ((size_t)b * SEQ + q0 + 16 * w + r) * DIM + h * HD;
#pragma unroll
    for (int nt = 0; nt < 8; nt++) {
        int d0 = nt * 8 + c2;
        float t0 = Tf[d0], t1 = Tf[d0 + 1];
        *(float2*)(obase + d0) =
            make_float2((o[nt][0] + t0) * inv1024, (o[nt][1] + t1) * inv1024);
        *(float2*)(obase + (size_t)8 * DIM + d0) =
            make_float2((o[nt][2] + t0) * inv1024, (o[nt][3] + t1) * inv1024);
    }
}

// ---------------------------------------------------------------------------
// Kernel 3: out = g_att @ W^T + b.  Single-pass fp16. (r12, proven)
// ---------------------------------------------------------------------------
__global__ void __launch_bounds__(256, 2) k3_linear(const float* __restrict__ Wg,
                                                    const float* __restrict__ bg,
                                                    float* __restrict__ Og) {
    extern __shared__ u32 smu[];
    u32* Xp = smu;             // fp16 A-pack : 4096 u32
    u32* Wp = smu + 4096;      // fp16 B-pack : 4224 u32

    int tid = threadIdx.x, lane = tid & 31, w = tid >> 5;
    int wm = w >> 2, wn = w & 3;
    int n0 = blockIdx.x << 7, m0 = blockIdx.y << 7;

    float acc[4][4][4];
#pragma unroll
    for (int i = 0; i < 4; i++)
#pragma unroll
        for (int j = 0; j < 4; j++)
#pragma unroll
            for (int t = 0; t < 4; t++) acc[i][j][t] = 0.f;

    int rb = tid >> 4, c4 = (tid & 15) << 2;
    for (int d0 = 0; d0 < DIM; d0 += 64) {
        __syncthreads();
#pragma unroll
        for (int it = 0; it < 8; it++) {
            int r = rb + (it << 4);
            stA16f(Xp, r, c4,
                   *(const float4*)(g_att + (size_t)(m0 + r) * DIM + d0 + c4));
            stB16f<16>(Wp, r, c4,
                       *(const float4*)(Wg + (size_t)(n0 + r) * DIM + d0 + c4));
        }
        __syncthreads();

#pragma unroll
        for (int ks = 0; ks < 4; ks++) {
            uint4 ah[4]; uint2 bh[4];
#pragma unroll
            for (int i = 0; i < 4; i++) ah[i] = ldA16(Xp, ks, wm * 4 + i, lane);
#pragma unroll
            for (int j = 0; j < 4; j++) bh[j] = ldB16<16>(Wp, ks, wn * 4 + j, lane);
#pragma unroll
            for (int i = 0; i < 4; i++)
#pragma unroll
                for (int j = 0; j < 4; j++)
                    mma16f(acc[i][j], ah[i], bh[j]);
        }
    }

#pragma unroll
    for (int i = 0; i < 4; i++)
#pragma unroll
        for (int j = 0; j < 4; j++) {
            int r = wm * 64 + i * 16 + (lane >> 2);
            int n = wn * 32 + j * 8 + ((lane & 3) << 1);
            float2 bb = *(const float2*)(bg + n0 + n);
            float* p = Og + (size_t)(m0 + r) * DIM + n0 + n;
            *(float2*)p = make_float2(acc[i][j][0] + bb.x, acc[i][j][1] + bb.y);
            *(float2*)(p + (size_t)8 * DIM) =
                make_float2(acc[i][j][2] + bb.x, acc[i][j][3] + bb.y);
        }
}

// ---------------------------------------------------------------------------

extern "C" void kernel_launch(void* const* d_in, const int* in_sizes, int n_in,
                              void* d_out, int out_size) {
    const float* Q = (const float*)d_in[0];
    const float* K = (const float*)d_in[1];
    const float* V = (const float*)d_in[2];
    const float* W = (const float*)d_in[3];
    const float* bias = (const float*)d_in[4];
    float* out = (float*)d_out;
    (void)in_sizes; (void)n_in; (void)out_size;

    const int smem1 = (4096 + 4224 + 128) * 4;   // 33792
    const int smem2 = 13632 * 4;                 // 54528
    const int smem3 = 8320 * 4;                  // 33280

    cudaFuncSetAttribute(k1_colsum, cudaFuncAttributeMaxDynamicSharedMemorySize, smem1);
    cudaFuncSetAttribute(k2_attnv,  cudaFuncAttributeMaxDynamicSharedMemorySize, smem2);
    cudaFuncSetAttribute(k3_linear, cudaFuncAttributeMaxDynamicSharedMemorySize, smem3);

    dim3 gAttn(SEQ / 128, NH, NB);          // 1024 CTAs
    k1_colsum<<<gAttn, 256, smem1>>>(Q, K);
    k2_attnv<<<gAttn, 256, smem2>>>(Q, K, V);

    dim3 gLin(DIM / 128, (NB * SEQ) / 128); // 512 CTAs
    k3_linear<<<gLin, 256, smem3>>>(W, bias, out);
}